// round 14
// baseline (speedup 1.0000x reference)
#include <cuda_runtime.h>
#include <cuda_fp16.h>
#include <math.h>
#include <cstdint>

#define BB 2048
#define DD 1024
#define UU 1024
#define HHU 256
#define FOURU (4*UU)     // 4096
#define FOURHU (4*HHU)   // 1024
#define KHYP (DD+UU+HHU) // 2304
#define N3 (3*FOURU)     // 12288

// ---------------------------------------------------------------------------
// scratch (static device arrays; no allocation allowed)
// ---------------------------------------------------------------------------
__device__ float g_z [BB * FOURHU];
__device__ float g_s [BB * FOURU];    // fused gate pre-activations
__device__ float g_px[BB * FOURU];
__device__ float g_ph[BB * FOURU];
__device__ int   g_cnt[16];           // per-128-row-block hyper completion count

// fp16 activations
__device__ __half g_ahyp[BB * KHYP];   // fp16 of [inputs|main_h|hyper_h]
__device__ __half g_aho [BB * HHU];    // fp16 of hyper_out
// transposed fp16 weights ([N, K] row-major, k-contiguous)
__device__ __half g_wthyp[FOURHU * KHYP];
__device__ __half g_wtall[N3 * HHU];   // dx_w^T | dh_w^T | db_w^T stacked on N
__device__ __half g_wtk[FOURU * UU];
__device__ __half g_wtr[FOURU * UU];

__device__ __forceinline__ float sigf(float x) { return 1.0f / (1.0f + expf(-x)); }

__device__ __forceinline__ uint32_t smem_u32(const void* p) {
    uint32_t a;
    asm("{ .reg .u64 t; cvta.to.shared.u64 t, %1; cvt.u32.u64 %0, t; }" : "=r"(a) : "l"(p));
    return a;
}
__device__ __forceinline__ void cpa16(uint32_t dst, const void* src) {
    asm volatile("cp.async.cg.shared.global [%0], [%1], 16;" :: "r"(dst), "l"(src));
}
#define CP_COMMIT() asm volatile("cp.async.commit_group;" ::: "memory")
#define CP_WAIT(n)  asm volatile("cp.async.wait_group %0;" :: "n"(n) : "memory")

__device__ __forceinline__ void ldsm4(uint32_t* r, uint32_t addr) {
    asm volatile("ldmatrix.sync.aligned.m8n8.x4.shared.b16 {%0,%1,%2,%3}, [%4];"
                 : "=r"(r[0]), "=r"(r[1]), "=r"(r[2]), "=r"(r[3]) : "r"(addr));
}
__device__ __forceinline__ void mma_f16(float* c, const uint32_t* a, uint32_t b0, uint32_t b1) {
    asm volatile("mma.sync.aligned.m16n8k16.row.col.f32.f16.f16.f32 "
                 "{%0,%1,%2,%3}, {%4,%5,%6,%7}, {%8,%9}, {%0,%1,%2,%3};"
                 : "+f"(c[0]), "+f"(c[1]), "+f"(c[2]), "+f"(c[3])
                 : "r"(a[0]), "r"(a[1]), "r"(a[2]), "r"(a[3]), "r"(b0), "r"(b1));
}

#define SROW 144

// ---------------------------------------------------------------------------
// 1-term GEMM core: C[M,N] = A[M,K] @ W[N,K]^T (+bias)
// CTA tile 128 x 256; 8 warps 2(m) x 4(n); warp tile 64x64; BK=64;
// 3-stage cp.async pipeline; 256 threads.
// ---------------------------------------------------------------------------
#define G_ABYTES (128 * SROW)                 // 18432
#define G_SSZ    ((128 + 256) * SROW)         // 55296
#define G_SMEM   (3 * G_SSZ)                  // 165888

__device__ __forceinline__
void gemm_core4(const __half* __restrict__ Ah, int lda,
                const __half* __restrict__ Wh, int ldw,
                const float* __restrict__ bias, float* __restrict__ C,
                int N, int K, char* smem, int bx, int by)
{
    const uint32_t sb = smem_u32(smem);
    const int tid  = threadIdx.x;
    const int lane = tid & 31;
    const int wid  = tid >> 5;
    const int warp_m = wid & 1;
    const int warp_n = wid >> 1;
    const int m0 = by * 128;
    const int n0 = bx * 256;

    const __half* pAh = Ah + (size_t)m0 * lda;
    const __half* pWh = Wh + (size_t)n0 * ldw;

    float acc[4][8][4];
    #pragma unroll
    for (int a = 0; a < 4; a++)
        #pragma unroll
        for (int b = 0; b < 8; b++)
            #pragma unroll
            for (int c = 0; c < 4; c++) acc[a][b][c] = 0.0f;

    const uint32_t fr  = lane & 15;
    const uint32_t fcb = (lane >> 4) * 16;
    const int lr = tid >> 3;        // 0..31
    const int lc = tid & 7;
    const int nch = K / 64;

    auto load_stage = [&](uint32_t base, int k0) {
        #pragma unroll
        for (int i = 0; i < 4; i++) {
            int row = lr + i * 32;
            cpa16(base + row * SROW + lc * 16, pAh + (size_t)row * lda + k0 + lc * 8);
        }
        #pragma unroll
        for (int i = 0; i < 8; i++) {
            int row = lr + i * 32;
            cpa16(base + G_ABYTES + row * SROW + lc * 16, pWh + (size_t)row * ldw + k0 + lc * 8);
        }
    };

    // preload stages 0 and 1 (nch >= 16 for all our shapes)
    load_stage(sb, 0);
    CP_COMMIT();
    load_stage(sb + G_SSZ, 64);
    CP_COMMIT();

    int buf = 0;
    int nbuf = 2;

    for (int kc = 0; kc < nch; kc++) {
        if (kc + 2 < nch) {
            load_stage(sb + nbuf * G_SSZ, (kc + 2) * 64);
            CP_COMMIT();
            nbuf = (nbuf == 2) ? 0 : nbuf + 1;
            CP_WAIT(2);
        } else if (kc + 1 < nch) {
            CP_WAIT(1);
        } else {
            CP_WAIT(0);
        }
        __syncthreads();

        const uint32_t stg = sb + buf * G_SSZ;
        buf = (buf == 2) ? 0 : buf + 1;
        #pragma unroll
        for (int s = 0; s < 4; s++) {
            const uint32_t kb = s * 32 + fcb;
            uint32_t ah[4][4];
            #pragma unroll
            for (int mt = 0; mt < 4; mt++)
                ldsm4(ah[mt], stg + (warp_m * 64 + mt * 16 + fr) * SROW + kb);
            #pragma unroll
            for (int np = 0; np < 4; np++) {
                uint32_t w[4];
                ldsm4(w, stg + G_ABYTES + (warp_n * 64 + np * 16 + fr) * SROW + kb);
                #pragma unroll
                for (int mt = 0; mt < 4; mt++) {
                    mma_f16(acc[mt][2*np],   ah[mt], w[0], w[2]);
                    mma_f16(acc[mt][2*np+1], ah[mt], w[1], w[3]);
                }
            }
        }
        __syncthreads();
    }

    const int er = lane >> 2;
    const int ec = (lane & 3) * 2;
    #pragma unroll
    for (int mt = 0; mt < 4; mt++) {
        const int row = m0 + warp_m * 64 + mt * 16 + er;
        #pragma unroll
        for (int nt = 0; nt < 8; nt++) {
            const int col = n0 + warp_n * 64 + nt * 8 + ec;
            float b0 = 0.f, b1 = 0.f;
            if (bias) { b0 = bias[col]; b1 = bias[col + 1]; }
            *(float2*)(C + (size_t)row * N + col) =
                make_float2(acc[mt][nt][0] + b0, acc[mt][nt][1] + b1);
            *(float2*)(C + (size_t)(row + 8) * N + col) =
                make_float2(acc[mt][nt][2] + b0, acc[mt][nt][3] + b1);
        }
    }
}

// ---------------------------------------------------------------------------
// gemm_all: hyper + px + ph in one flat-grid launch.
// blocks [0,64): hyper (N=1024, K=2304) -- scheduled FIRST; each releases a
//                per-rowblock counter after its tile is in gmem.
// blocks [64,320): px (N=4096, K=1024)
// blocks [320,576): ph (N=4096, K=1024)
// ---------------------------------------------------------------------------
__global__ __launch_bounds__(256, 1)
void gemm_all(const __half* __restrict__ ahyp,
              const __half* __restrict__ wtk, const __half* __restrict__ wtr,
              const __half* __restrict__ wthyp,
              const float* __restrict__ bias, const float* __restrict__ hyper_bias,
              float* __restrict__ px, float* __restrict__ ph, float* __restrict__ z,
              int* __restrict__ cnt)
{
    extern __shared__ char smem[];
    const int b = blockIdx.x;
    if (b < 64) {
        const int by = b >> 2;
        gemm_core4(ahyp, KHYP, wthyp, KHYP, hyper_bias, z, FOURHU, KHYP,
                   smem, b & 3, by);
        __syncthreads();
        __threadfence();
        if (threadIdx.x == 0)
            asm volatile("red.release.gpu.global.add.s32 [%0], %1;"
                         :: "l"(&cnt[by]), "r"(1) : "memory");
    } else if (b < 320) {
        const int i = b - 64;
        gemm_core4(ahyp, KHYP, wtk, UU, bias, px, FOURU, UU,
                   smem, i & 15, i >> 4);
    } else {
        const int i = b - 320;
        gemm_core4(ahyp + DD, KHYP, wtr, UU, nullptr, ph, FOURU, UU,
                   smem, i & 15, i >> 4);
    }
}

// ---------------------------------------------------------------------------
// hyper pointwise, flag-gated: 16 CTAs, each waits for its rowblock's 4 hyper
// producers then computes hyper_out/hyper_c_new/aho for 128 rows.
// No smem, low regs -> co-resident with gemm_all CTAs.
// ---------------------------------------------------------------------------
__global__ __launch_bounds__(256)
void hyper_pointwise_flag(const float* __restrict__ z,
                          const float* __restrict__ hyper_c,
                          float* __restrict__ hyper_out,
                          float* __restrict__ hyper_c_new,
                          __half* __restrict__ hoh,
                          const int* __restrict__ cnt)
{
    const int by = blockIdx.x;       // 0..15
    if (threadIdx.x == 0) {
        int v;
        do {
            asm volatile("ld.acquire.gpu.b32 %0, [%1];" : "=r"(v) : "l"(&cnt[by]) : "memory");
            if (v < 4) __nanosleep(256);
        } while (v < 4);
    }
    __syncthreads();

    const int m0 = by * 128;
    for (int idx = threadIdx.x; idx < 128 * HHU; idx += 256) {
        const int r = idx >> 8;
        const int u = idx & 255;
        const int gr = m0 + r;
        const float* zr = z + (size_t)gr * FOURHU;
        float hi = zr[u];
        float hf = zr[HHU + u];
        float hg = zr[2 * HHU + u];
        float ho = zr[3 * HHU + u];
        float c = sigf(hf) * hyper_c[(size_t)gr * HHU + u] + sigf(hi) * tanhf(hg);
        hyper_c_new[(size_t)gr * HHU + u] = c;
        float out = sigf(ho) * tanhf(c);
        hyper_out[(size_t)gr * HHU + u] = out;
        hoh[(size_t)gr * HHU + u] = __float2half_rn(out);
    }
}

// ---------------------------------------------------------------------------
// gemm_s: fused d_x/d_h/d_b GEMM + gate combine, with px/ph smem prefetch.
// ---------------------------------------------------------------------------
#define S_ATILE  (128 * SROW)
#define S_WOFF   (4 * S_ATILE)
#define S_PXOFF  (S_WOFF + 2 * S_ATILE)   // 110592
#define S_PXROW  528
#define S_SMEM   (S_PXOFF + 128 * S_PXROW) // 178176

__global__ __launch_bounds__(256, 1)
void gemm_s(const __half* __restrict__ A,
            const __half* __restrict__ Wall,
            const float* __restrict__ bx, const float* __restrict__ bh,
            const float* __restrict__ bb,
            const float* __restrict__ px, const float* __restrict__ ph,
            float* __restrict__ S)
{
    extern __shared__ char smem[];
    const uint32_t sb = smem_u32(smem);
    const int tid  = threadIdx.x;
    const int lane = tid & 31;
    const int wid  = tid >> 5;
    const int warp_m = wid & 1;
    const int warp_n = wid >> 1;
    const int m0 = blockIdx.y * 128;
    const int n0 = blockIdx.x * 128;

    const __half* pA = A + (size_t)m0 * HHU;

    const uint32_t fr  = lane & 15;
    const uint32_t fcb = (lane >> 4) * 16;
    const int lr = tid >> 3;
    const int lc = tid & 7;

    #pragma unroll
    for (int c = 0; c < 4; c++)
        #pragma unroll
        for (int i = 0; i < 4; i++) {
            int row = lr + i * 32;
            cpa16(sb + c * S_ATILE + row * SROW + lc * 16,
                  pA + (size_t)row * HHU + c * 64 + lc * 8);
        }
    auto load_w = [&](int t, int kc, int buf) {
        const __half* pW = Wall + (size_t)t * FOURU * HHU + (size_t)n0 * HHU;
        #pragma unroll
        for (int i = 0; i < 4; i++) {
            int row = lr + i * 32;
            cpa16(sb + S_WOFF + buf * S_ATILE + row * SROW + lc * 16,
                  pW + (size_t)row * HHU + kc * 64 + lc * 8);
        }
    };
    auto load_p = [&](const float* __restrict__ P) {
        #pragma unroll
        for (int it = 0; it < 16; it++) {
            int idx = tid + it * 256;
            int row = idx >> 5;
            int c16 = idx & 31;
            cpa16(sb + S_PXOFF + row * S_PXROW + c16 * 16,
                  P + (size_t)(m0 + row) * FOURU + n0 + c16 * 4);
        }
    };

    load_w(0, 0, 0);
    CP_COMMIT();

    float s_acc[4][4][4];
    #pragma unroll
    for (int a = 0; a < 4; a++)
        #pragma unroll
        for (int b = 0; b < 4; b++)
            #pragma unroll
            for (int c = 0; c < 4; c++) s_acc[a][b][c] = 0.0f;

    float acc[4][4][4];
    #pragma unroll
    for (int a = 0; a < 4; a++)
        #pragma unroll
        for (int b = 0; b < 4; b++)
            #pragma unroll
            for (int c = 0; c < 4; c++) acc[a][b][c] = 0.0f;

    const int er = lane >> 2;
    const int ec = (lane & 3) * 2;

    for (int i = 0; i < 12; i++) {
        const int kc = i & 3;
        if (i + 1 < 12) {
            load_w((i + 1) >> 2, (i + 1) & 3, (i + 1) & 1);
            if (i == 0) load_p(px);
            if (i == 4) load_p(ph);
            CP_COMMIT();
            CP_WAIT(1);
        } else {
            CP_WAIT(0);
        }
        __syncthreads();

        const uint32_t wb = sb + S_WOFF + (i & 1) * S_ATILE;
        const uint32_t ab = sb + kc * S_ATILE;
        #pragma unroll
        for (int s = 0; s < 4; s++) {
            const uint32_t kb = s * 32 + fcb;
            uint32_t ah[4][4];
            #pragma unroll
            for (int mt = 0; mt < 4; mt++)
                ldsm4(ah[mt], ab + (warp_m * 64 + mt * 16 + fr) * SROW + kb);
            #pragma unroll
            for (int np = 0; np < 2; np++) {
                uint32_t w[4];
                ldsm4(w, wb + (warp_n * 32 + np * 16 + fr) * SROW + kb);
                #pragma unroll
                for (int mt = 0; mt < 4; mt++) {
                    mma_f16(acc[mt][2*np],   ah[mt], w[0], w[2]);
                    mma_f16(acc[mt][2*np+1], ah[mt], w[1], w[3]);
                }
            }
        }

        if (kc == 3) {
            const int t = i >> 2;
            #pragma unroll
            for (int mt = 0; mt < 4; mt++) {
                const int rl = warp_m * 64 + mt * 16 + er;
                #pragma unroll
                for (int nt = 0; nt < 4; nt++) {
                    const int cl = warp_n * 32 + nt * 8 + ec;
                    const int col = n0 + cl;
                    if (t < 2) {
                        float2 p0 = *(const float2*)(smem + S_PXOFF + rl * S_PXROW + cl * 4);
                        float2 p1 = *(const float2*)(smem + S_PXOFF + (rl + 8) * S_PXROW + cl * 4);
                        const float* bp = (t == 0) ? bx : bh;
                        float b0 = bp[col], b1 = bp[col + 1];
                        s_acc[mt][nt][0] += (acc[mt][nt][0] + b0) * p0.x;
                        s_acc[mt][nt][1] += (acc[mt][nt][1] + b1) * p0.y;
                        s_acc[mt][nt][2] += (acc[mt][nt][2] + b0) * p1.x;
                        s_acc[mt][nt][3] += (acc[mt][nt][3] + b1) * p1.y;
                    } else {
                        float b0 = bb[col], b1 = bb[col + 1];
                        s_acc[mt][nt][0] += acc[mt][nt][0] + b0;
                        s_acc[mt][nt][1] += acc[mt][nt][1] + b1;
                        s_acc[mt][nt][2] += acc[mt][nt][2] + b0;
                        s_acc[mt][nt][3] += acc[mt][nt][3] + b1;
                    }
                    #pragma unroll
                    for (int c = 0; c < 4; c++) acc[mt][nt][c] = 0.0f;
                }
            }
        }
        __syncthreads();
    }

    #pragma unroll
    for (int mt = 0; mt < 4; mt++) {
        const int row = m0 + warp_m * 64 + mt * 16 + er;
        #pragma unroll
        for (int nt = 0; nt < 4; nt++) {
            const int col = n0 + warp_n * 32 + nt * 8 + ec;
            *(float2*)(S + (size_t)row * FOURU + col) =
                make_float2(s_acc[mt][nt][0], s_acc[mt][nt][1]);
            *(float2*)(S + (size_t)(row + 8) * FOURU + col) =
                make_float2(s_acc[mt][nt][2], s_acc[mt][nt][3]);
        }
    }
}

// ---------------------------------------------------------------------------
// prep kernels
// ---------------------------------------------------------------------------
__global__ void concat_fp16(const float* __restrict__ inputs,
                            const float* __restrict__ main_h,
                            const float* __restrict__ hyper_h,
                            __half* __restrict__ Dh)
{
    int i4 = blockIdx.x * blockDim.x + threadIdx.x;
    if (i4 >= BB * KHYP / 4) return;
    int row = i4 / (KHYP / 4);
    int c4  = (i4 - row * (KHYP / 4)) * 4;
    const float* src;
    if (c4 < DD)            src = inputs  + (size_t)row * DD  + c4;
    else if (c4 < DD + UU)  src = main_h  + (size_t)row * UU  + (c4 - DD);
    else                    src = hyper_h + (size_t)row * HHU + (c4 - DD - UU);
    float4 v = *(const float4*)src;
    size_t o = (size_t)row * KHYP + c4;
    unsigned short hs[4];
    hs[0] = __half_as_ushort(__float2half_rn(v.x));
    hs[1] = __half_as_ushort(__float2half_rn(v.y));
    hs[2] = __half_as_ushort(__float2half_rn(v.z));
    hs[3] = __half_as_ushort(__float2half_rn(v.w));
    *(uint2*)(Dh + o) = make_uint2((uint32_t)hs[0] | ((uint32_t)hs[1] << 16),
                                   (uint32_t)hs[2] | ((uint32_t)hs[3] << 16));
}

__device__ __forceinline__ void trans_tile(const float* __restrict__ W,
                                           __half* __restrict__ Th,
                                           int N, int dstLd, int kOff,
                                           int n0, int k0)
{
    __shared__ float t[64][33];
    const int tx = threadIdx.x, ty = threadIdx.y;   // 32 x 8
    #pragma unroll
    for (int i = 0; i < 8; i++)
        t[ty + i * 8][tx] = W[(size_t)(k0 + ty + i * 8) * N + n0 + tx];
    __syncthreads();
    #pragma unroll
    for (int j = 0; j < 4; j++) {
        int n = ty + j * 8;
        float v0 = t[tx * 2][n], v1 = t[tx * 2 + 1][n];
        uint32_t pk = (uint32_t)__half_as_ushort(__float2half_rn(v0))
                    | ((uint32_t)__half_as_ushort(__float2half_rn(v1)) << 16);
        *(uint32_t*)(Th + (size_t)(n0 + n) * dstLd + kOff + k0 + tx * 2) = pk;
    }
}

__global__ void trans_d3(const float* __restrict__ w0, const float* __restrict__ w1,
                         const float* __restrict__ w2, __half* __restrict__ Tall)
{
    const float* W = (blockIdx.z == 0) ? w0 : (blockIdx.z == 1) ? w1 : w2;
    trans_tile(W, Tall + (size_t)blockIdx.z * FOURU * HHU, FOURU, HHU, 0,
               blockIdx.x * 32, blockIdx.y * 64);
}

__global__ void trans_kr(const float* __restrict__ kw, const float* __restrict__ rw,
                         __half* __restrict__ Tk, __half* __restrict__ Tr)
{
    const float* W = blockIdx.z ? rw : kw;
    __half* T = blockIdx.z ? Tr : Tk;
    trans_tile(W, T, FOURU, UU, 0, blockIdx.x * 32, blockIdx.y * 64);
}

__global__ void trans_hyp(const float* __restrict__ hk, const float* __restrict__ hr,
                          __half* __restrict__ T)
{
    if (blockIdx.z == 0) {
        trans_tile(hk, T, FOURHU, KHYP, 0, blockIdx.x * 32, blockIdx.y * 64);
    } else {
        if (blockIdx.y >= HHU / 64) return;
        trans_tile(hr, T, FOURHU, KHYP, DD + UU, blockIdx.x * 32, blockIdx.y * 64);
    }
}

// ---------------------------------------------------------------------------
// LN epilogue
// ---------------------------------------------------------------------------
__device__ __forceinline__ void block_reduce2(float& a, float& b, float* sm)
{
    __syncthreads();
    #pragma unroll
    for (int o = 16; o > 0; o >>= 1) {
        a += __shfl_down_sync(0xffffffffu, a, o);
        b += __shfl_down_sync(0xffffffffu, b, o);
    }
    int w = threadIdx.x >> 5, l = threadIdx.x & 31;
    if (l == 0) { sm[w] = a; sm[32 + w] = b; }
    __syncthreads();
    if (w == 0) {
        int nw = blockDim.x >> 5;
        a = (l < nw) ? sm[l] : 0.0f;
        b = (l < nw) ? sm[32 + l] : 0.0f;
        #pragma unroll
        for (int o = 16; o > 0; o >>= 1) {
            a += __shfl_down_sync(0xffffffffu, a, o);
            b += __shfl_down_sync(0xffffffffu, b, o);
        }
        if (l == 0) { sm[0] = a; sm[32] = b; }
    }
    __syncthreads();
    a = sm[0];
    b = sm[32];
}

__global__ __launch_bounds__(512)
void main_epilogue(const float* __restrict__ S, const float* __restrict__ main_c,
                   float* __restrict__ out_h, float* __restrict__ out_c)
{
    __shared__ float sm[64];
    const int b = blockIdx.x;
    const int t = threadIdx.x;
    const size_t b4 = (size_t)b * FOURU;

    float s[8];
    float sum = 0.0f, sq = 0.0f;
    #pragma unroll
    for (int r = 0; r < 8; r++) {
        float v = S[b4 + t + r * 512];
        s[r] = v;
        sum += v;
        sq = fmaf(v, v, sq);
    }
    block_reduce2(sum, sq, sm);
    float mean = sum * (1.0f / 4096.0f);
    float var = sq * (1.0f / 4096.0f) - mean * mean;
    float inv = rsqrtf(var + 1e-3f);

    float i0 = (s[0] - mean) * inv, i1 = (s[1] - mean) * inv;
    float f0 = (s[2] - mean) * inv, f1 = (s[3] - mean) * inv;
    float g0 = (s[4] - mean) * inv, g1 = (s[5] - mean) * inv;
    float o0 = (s[6] - mean) * inv, o1 = (s[7] - mean) * inv;

    const size_t cb = (size_t)b * UU;
    float c0 = sigf(f0) * main_c[cb + t]       + sigf(i0) * tanhf(g0);
    float c1 = sigf(f1) * main_c[cb + t + 512] + sigf(i1) * tanhf(g1);

    float sum2 = c0 + c1;
    float sq2 = fmaf(c0, c0, c1 * c1);
    block_reduce2(sum2, sq2, sm);
    float mean2 = sum2 * (1.0f / 1024.0f);
    float var2 = sq2 * (1.0f / 1024.0f) - mean2 * mean2;
    float inv2 = rsqrtf(var2 + 1e-3f);

    float h0 = sigf(o0) * tanhf((c0 - mean2) * inv2);
    float h1 = sigf(o1) * tanhf((c1 - mean2) * inv2);

    out_c[cb + t] = c0;
    out_c[cb + t + 512] = c1;
    out_h[cb + t] = h0;
    out_h[cb + t + 512] = h1;
}

// ---------------------------------------------------------------------------
// launch
// ---------------------------------------------------------------------------
static cudaStream_t make_stream() {
    cudaStream_t s;
    cudaStreamCreateWithFlags(&s, cudaStreamNonBlocking);
    return s;
}
static cudaEvent_t make_event() {
    cudaEvent_t e;
    cudaEventCreateWithFlags(&e, cudaEventDisableTiming);
    return e;
}

extern "C" void kernel_launch(void* const* d_in, const int* in_sizes, int n_in,
                              void* d_out, int out_size)
{
    const float* inputs       = (const float*)d_in[0];
    const float* main_h       = (const float*)d_in[1];
    const float* main_c       = (const float*)d_in[2];
    const float* hyper_h      = (const float*)d_in[3];
    const float* hyper_c      = (const float*)d_in[4];
    const float* kernel_w     = (const float*)d_in[5];
    const float* rec_w        = (const float*)d_in[6];
    const float* bias         = (const float*)d_in[7];
    const float* hyper_kernel = (const float*)d_in[8];
    const float* hyper_rec    = (const float*)d_in[9];
    const float* hyper_bias   = (const float*)d_in[10];
    const float* dx_w         = (const float*)d_in[11];
    const float* dx_b         = (const float*)d_in[12];
    const float* dh_w         = (const float*)d_in[13];
    const float* dh_b         = (const float*)d_in[14];
    const float* db_w         = (const float*)d_in[15];
    const float* db_b         = (const float*)d_in[16];

    float* out = (float*)d_out;
    float* out_h  = out;
    float* out_c  = out + (size_t)BB * UU;
    float* out_ho = out + (size_t)2 * BB * UU;
    float* out_hc = out_ho + (size_t)BB * HHU;

    float *z, *s, *px, *phv;
    int* cnt;
    cudaGetSymbolAddress((void**)&z,   g_z);
    cudaGetSymbolAddress((void**)&s,   g_s);
    cudaGetSymbolAddress((void**)&px,  g_px);
    cudaGetSymbolAddress((void**)&phv, g_ph);
    cudaGetSymbolAddress((void**)&cnt, g_cnt);

    __half *ahyp, *aho, *wthyp, *wtall, *wtk, *wtr;
    cudaGetSymbolAddress((void**)&ahyp,  g_ahyp);
    cudaGetSymbolAddress((void**)&aho,   g_aho);
    cudaGetSymbolAddress((void**)&wthyp, g_wthyp);
    cudaGetSymbolAddress((void**)&wtall, g_wtall);
    cudaGetSymbolAddress((void**)&wtk,   g_wtk);
    cudaGetSymbolAddress((void**)&wtr,   g_wtr);

    cudaFuncSetAttribute(gemm_all, cudaFuncAttributeMaxDynamicSharedMemorySize, G_SMEM);
    cudaFuncSetAttribute(gemm_s,   cudaFuncAttributeMaxDynamicSharedMemorySize, S_SMEM);

    // One-time resources (created outside capture on first call; reused after).
    static cudaStream_t sB = make_stream();
    static cudaStream_t sC = make_stream();
    static cudaEvent_t evRoot  = make_event();
    static cudaEvent_t evHypW  = make_event();
    static cudaEvent_t evD3    = make_event();
    static cudaEvent_t evKR    = make_event();
    static cudaEvent_t evPW    = make_event();

    dim3 tb(32, 8);

    // counter reset BEFORE the fork so every stream is ordered after it
    cudaMemsetAsync(cnt, 0, 16 * sizeof(int), 0);

    // ---- fork side streams ----
    cudaEventRecord(evRoot, 0);
    cudaStreamWaitEvent(sB, evRoot, 0);
    cudaStreamWaitEvent(sC, evRoot, 0);

    // three concurrent prep branches
    concat_fp16<<<(BB * KHYP / 4 + 255) / 256, 256>>>(inputs, main_h, hyper_h, ahyp);

    trans_kr<<<dim3(FOURU/32, UU/64, 2), tb, 0, sC>>>(kernel_w, rec_w, wtk, wtr);
    cudaEventRecord(evKR, sC);

    trans_hyp<<<dim3(FOURHU/32, (DD+UU)/64, 2), tb, 0, sB>>>(hyper_kernel, hyper_rec, wthyp);
    cudaEventRecord(evHypW, sB);
    trans_d3 <<<dim3(FOURU/32, HHU/64, 3), tb, 0, sB>>>(dx_w, dh_w, db_w, wtall);
    cudaEventRecord(evD3, sB);

    // ---- combined GEMM launch (hyper tiles first; releases cnt flags) ----
    cudaStreamWaitEvent(0, evKR, 0);
    cudaStreamWaitEvent(0, evHypW, 0);
    gemm_all<<<576, 256, G_SMEM>>>(ahyp, wtk, wtr, wthyp, bias, hyper_bias,
                                   px, phv, z, cnt);

    // ---- flag-gated pointwise, CONCURRENT with gemm_all on sB ----
    hyper_pointwise_flag<<<16, 256, 0, sB>>>(z, hyper_c, out_ho, out_hc, aho, cnt);
    cudaEventRecord(evPW, sB);

    // ---- fused d-GEMM + gate combine -> s (after gemm_all + pointwise + d3) ----
    cudaStreamWaitEvent(0, evPW, 0);
    cudaStreamWaitEvent(0, evD3, 0);
    gemm_s<<<dim3(FOURU/128, BB/128), 256, S_SMEM>>>(
        aho, wtall, dx_b, dh_b, db_b, px, phv, s);

    main_epilogue<<<BB, 512>>>(s, main_c, out_h, out_c);
}

// round 15
// speedup vs baseline: 1.3897x; 1.3897x over previous
#include <cuda_runtime.h>
#include <cuda_fp16.h>
#include <math.h>
#include <cstdint>

#define BB 2048
#define DD 1024
#define UU 1024
#define HHU 256
#define FOURU (4*UU)     // 4096
#define FOURHU (4*HHU)   // 1024
#define KHYP (DD+UU+HHU) // 2304
#define N3 (3*FOURU)     // 12288

// ---------------------------------------------------------------------------
// scratch (static device arrays; no allocation allowed)
// ---------------------------------------------------------------------------
__device__ float g_z [BB * FOURHU];
__device__ float g_s [BB * FOURU];    // fused gate pre-activations
__device__ float g_px[BB * FOURU];
__device__ float g_ph[BB * FOURU];

// fp16 activations
__device__ __half g_ahyp[BB * KHYP];   // fp16 of [inputs|main_h|hyper_h]
__device__ __half g_aho [BB * HHU];    // fp16 of hyper_out
// transposed fp16 weights ([N, K] row-major, k-contiguous)
__device__ __half g_wthyp[FOURHU * KHYP];
__device__ __half g_wtall[N3 * HHU];   // dx_w^T | dh_w^T | db_w^T stacked on N
__device__ __half g_wtk[FOURU * UU];
__device__ __half g_wtr[FOURU * UU];

__device__ __forceinline__ float sigf(float x) { return 1.0f / (1.0f + expf(-x)); }

__device__ __forceinline__ uint32_t smem_u32(const void* p) {
    uint32_t a;
    asm("{ .reg .u64 t; cvta.to.shared.u64 t, %1; cvt.u32.u64 %0, t; }" : "=r"(a) : "l"(p));
    return a;
}
__device__ __forceinline__ void cpa16(uint32_t dst, const void* src) {
    asm volatile("cp.async.cg.shared.global [%0], [%1], 16;" :: "r"(dst), "l"(src));
}
#define CP_COMMIT() asm volatile("cp.async.commit_group;" ::: "memory")
#define CP_WAIT(n)  asm volatile("cp.async.wait_group %0;" :: "n"(n) : "memory")

__device__ __forceinline__ void ldsm4(uint32_t* r, uint32_t addr) {
    asm volatile("ldmatrix.sync.aligned.m8n8.x4.shared.b16 {%0,%1,%2,%3}, [%4];"
                 : "=r"(r[0]), "=r"(r[1]), "=r"(r[2]), "=r"(r[3]) : "r"(addr));
}
__device__ __forceinline__ void mma_f16(float* c, const uint32_t* a, uint32_t b0, uint32_t b1) {
    asm volatile("mma.sync.aligned.m16n8k16.row.col.f32.f16.f16.f32 "
                 "{%0,%1,%2,%3}, {%4,%5,%6,%7}, {%8,%9}, {%0,%1,%2,%3};"
                 : "+f"(c[0]), "+f"(c[1]), "+f"(c[2]), "+f"(c[3])
                 : "r"(a[0]), "r"(a[1]), "r"(a[2]), "r"(a[3]), "r"(b0), "r"(b1));
}

#define SROW 144

// ---------------------------------------------------------------------------
// 1-term GEMM core: C[M,N] = A[M,K] @ W[N,K]^T (+bias)
// CTA tile 128 x 256; 8 warps 2(m) x 4(n); warp tile 64x64; BK=64;
// 3-stage cp.async pipeline; 256 threads.
// ---------------------------------------------------------------------------
#define G_ABYTES (128 * SROW)                 // 18432
#define G_SSZ    ((128 + 256) * SROW)         // 55296
#define G_SMEM   (3 * G_SSZ)                  // 165888

__device__ __forceinline__
void gemm_core4(const __half* __restrict__ Ah, int lda,
                const __half* __restrict__ Wh, int ldw,
                const float* __restrict__ bias, float* __restrict__ C,
                int N, int K, char* smem, int bx, int by)
{
    const uint32_t sb = smem_u32(smem);
    const int tid  = threadIdx.x;
    const int lane = tid & 31;
    const int wid  = tid >> 5;
    const int warp_m = wid & 1;
    const int warp_n = wid >> 1;
    const int m0 = by * 128;
    const int n0 = bx * 256;

    const __half* pAh = Ah + (size_t)m0 * lda;
    const __half* pWh = Wh + (size_t)n0 * ldw;

    float acc[4][8][4];
    #pragma unroll
    for (int a = 0; a < 4; a++)
        #pragma unroll
        for (int b = 0; b < 8; b++)
            #pragma unroll
            for (int c = 0; c < 4; c++) acc[a][b][c] = 0.0f;

    const uint32_t fr  = lane & 15;
    const uint32_t fcb = (lane >> 4) * 16;
    const int lr = tid >> 3;        // 0..31
    const int lc = tid & 7;
    const int nch = K / 64;

    auto load_stage = [&](uint32_t base, int k0) {
        #pragma unroll
        for (int i = 0; i < 4; i++) {
            int row = lr + i * 32;
            cpa16(base + row * SROW + lc * 16, pAh + (size_t)row * lda + k0 + lc * 8);
        }
        #pragma unroll
        for (int i = 0; i < 8; i++) {
            int row = lr + i * 32;
            cpa16(base + G_ABYTES + row * SROW + lc * 16, pWh + (size_t)row * ldw + k0 + lc * 8);
        }
    };

    load_stage(sb, 0);
    CP_COMMIT();
    load_stage(sb + G_SSZ, 64);
    CP_COMMIT();

    int buf = 0;
    int nbuf = 2;

    for (int kc = 0; kc < nch; kc++) {
        if (kc + 2 < nch) {
            load_stage(sb + nbuf * G_SSZ, (kc + 2) * 64);
            CP_COMMIT();
            nbuf = (nbuf == 2) ? 0 : nbuf + 1;
            CP_WAIT(2);
        } else if (kc + 1 < nch) {
            CP_WAIT(1);
        } else {
            CP_WAIT(0);
        }
        __syncthreads();

        const uint32_t stg = sb + buf * G_SSZ;
        buf = (buf == 2) ? 0 : buf + 1;
        #pragma unroll
        for (int s = 0; s < 4; s++) {
            const uint32_t kb = s * 32 + fcb;
            uint32_t ah[4][4];
            #pragma unroll
            for (int mt = 0; mt < 4; mt++)
                ldsm4(ah[mt], stg + (warp_m * 64 + mt * 16 + fr) * SROW + kb);
            #pragma unroll
            for (int np = 0; np < 4; np++) {
                uint32_t w[4];
                ldsm4(w, stg + G_ABYTES + (warp_n * 64 + np * 16 + fr) * SROW + kb);
                #pragma unroll
                for (int mt = 0; mt < 4; mt++) {
                    mma_f16(acc[mt][2*np],   ah[mt], w[0], w[2]);
                    mma_f16(acc[mt][2*np+1], ah[mt], w[1], w[3]);
                }
            }
        }
        __syncthreads();
    }

    const int er = lane >> 2;
    const int ec = (lane & 3) * 2;
    #pragma unroll
    for (int mt = 0; mt < 4; mt++) {
        const int row = m0 + warp_m * 64 + mt * 16 + er;
        #pragma unroll
        for (int nt = 0; nt < 8; nt++) {
            const int col = n0 + warp_n * 64 + nt * 8 + ec;
            float b0 = 0.f, b1 = 0.f;
            if (bias) { b0 = bias[col]; b1 = bias[col + 1]; }
            *(float2*)(C + (size_t)row * N + col) =
                make_float2(acc[mt][nt][0] + b0, acc[mt][nt][1] + b1);
            *(float2*)(C + (size_t)(row + 8) * N + col) =
                make_float2(acc[mt][nt][2] + b0, acc[mt][nt][3] + b1);
        }
    }
}

// ---------------------------------------------------------------------------
// gemm_all: hyper + px + ph in one flat-grid launch.
// ---------------------------------------------------------------------------
__global__ __launch_bounds__(256, 1)
void gemm_all(const __half* __restrict__ ahyp,
              const __half* __restrict__ wtk, const __half* __restrict__ wtr,
              const __half* __restrict__ wthyp,
              const float* __restrict__ bias, const float* __restrict__ hyper_bias,
              float* __restrict__ px, float* __restrict__ ph, float* __restrict__ z)
{
    extern __shared__ char smem[];
    const int b = blockIdx.x;
    if (b < 64) {
        gemm_core4(ahyp, KHYP, wthyp, KHYP, hyper_bias, z, FOURHU, KHYP,
                   smem, b & 3, b >> 2);
    } else if (b < 320) {
        const int i = b - 64;
        gemm_core4(ahyp, KHYP, wtk, UU, bias, px, FOURU, UU,
                   smem, i & 15, i >> 4);
    } else {
        const int i = b - 320;
        gemm_core4(ahyp + DD, KHYP, wtr, UU, nullptr, ph, FOURU, UU,
                   smem, i & 15, i >> 4);
    }
}

// ---------------------------------------------------------------------------
// gemm_s: fused d_x/d_h/d_b GEMM + gate combine, px/ph via smem prefetch.
// NEW shape: CTA tile 64(m) x 128(n); 128 threads; 4 warps 1(m) x 4(n);
// warp tile 64x32 (same per-warp shape as before). 105 KB smem -> 2 CTAs/SM.
// ---------------------------------------------------------------------------
#define S_ATILE  (64 * SROW)               // 9216
#define S_WTILE  (128 * SROW)              // 18432
#define S_WOFF   (4 * S_ATILE)             // 36864
#define S_PXOFF  (S_WOFF + 2 * S_WTILE)    // 73728
#define S_PXROW  528                        // 132 floats per row (pad)
#define S_SMEM   (S_PXOFF + 64 * S_PXROW)  // 107520

__global__ __launch_bounds__(128, 2)
void gemm_s(const __half* __restrict__ A,          // aho [2048,256]
            const __half* __restrict__ Wall,       // [12288,256]
            const float* __restrict__ bx, const float* __restrict__ bh,
            const float* __restrict__ bb,
            const float* __restrict__ px, const float* __restrict__ ph,
            float* __restrict__ S)
{
    extern __shared__ char smem[];
    const uint32_t sb = smem_u32(smem);
    const int tid  = threadIdx.x;
    const int lane = tid & 31;
    const int warp_n = tid >> 5;            // 0..3
    const int m0 = blockIdx.y * 64;
    const int n0 = blockIdx.x * 128;

    const __half* pA = A + (size_t)m0 * HHU;

    const uint32_t fr  = lane & 15;
    const uint32_t fcb = (lane >> 4) * 16;
    const int lr = tid >> 3;                // 0..15
    const int lc = tid & 7;

    // load full A (4 chunks of 64x64 halfs)
    #pragma unroll
    for (int c = 0; c < 4; c++)
        #pragma unroll
        for (int i = 0; i < 4; i++) {
            int row = lr + i * 16;
            cpa16(sb + c * S_ATILE + row * SROW + lc * 16,
                  pA + (size_t)row * HHU + c * 64 + lc * 8);
        }
    auto load_w = [&](int t, int kc, int buf) {
        const __half* pW = Wall + (size_t)t * FOURU * HHU + (size_t)n0 * HHU;
        #pragma unroll
        for (int i = 0; i < 8; i++) {
            int row = lr + i * 16;
            cpa16(sb + S_WOFF + buf * S_WTILE + row * SROW + lc * 16,
                  pW + (size_t)row * HHU + kc * 64 + lc * 8);
        }
    };
    auto load_p = [&](const float* __restrict__ P) {
        #pragma unroll
        for (int it = 0; it < 16; it++) {
            int idx = tid + it * 128;       // 0..2047 16B chunks
            int row = idx >> 5;             // 0..63
            int c16 = idx & 31;
            cpa16(sb + S_PXOFF + row * S_PXROW + c16 * 16,
                  P + (size_t)(m0 + row) * FOURU + n0 + c16 * 4);
        }
    };

    load_w(0, 0, 0);
    CP_COMMIT();

    float s_acc[4][4][4];
    #pragma unroll
    for (int a = 0; a < 4; a++)
        #pragma unroll
        for (int b = 0; b < 4; b++)
            #pragma unroll
            for (int c = 0; c < 4; c++) s_acc[a][b][c] = 0.0f;

    float acc[4][4][4];
    #pragma unroll
    for (int a = 0; a < 4; a++)
        #pragma unroll
        for (int b = 0; b < 4; b++)
            #pragma unroll
            for (int c = 0; c < 4; c++) acc[a][b][c] = 0.0f;

    const int er = lane >> 2;
    const int ec = (lane & 3) * 2;

    for (int i = 0; i < 12; i++) {
        const int kc = i & 3;
        if (i + 1 < 12) {
            load_w((i + 1) >> 2, (i + 1) & 3, (i + 1) & 1);
            if (i == 0) load_p(px);   // arrives with group; used end of iter 3
            if (i == 4) load_p(ph);   // same buffer; used end of iter 7
            CP_COMMIT();
            CP_WAIT(1);
        } else {
            CP_WAIT(0);
        }
        __syncthreads();

        const uint32_t wb = sb + S_WOFF + (i & 1) * S_WTILE;
        const uint32_t ab = sb + kc * S_ATILE;
        #pragma unroll
        for (int s = 0; s < 4; s++) {
            const uint32_t kb = s * 32 + fcb;
            uint32_t ah[4][4];
            #pragma unroll
            for (int mt = 0; mt < 4; mt++)
                ldsm4(ah[mt], ab + (mt * 16 + fr) * SROW + kb);
            #pragma unroll
            for (int np = 0; np < 2; np++) {
                uint32_t w[4];
                ldsm4(w, wb + (warp_n * 32 + np * 16 + fr) * SROW + kb);
                #pragma unroll
                for (int mt = 0; mt < 4; mt++) {
                    mma_f16(acc[mt][2*np],   ah[mt], w[0], w[2]);
                    mma_f16(acc[mt][2*np+1], ah[mt], w[1], w[3]);
                }
            }
        }

        if (kc == 3) {
            const int t = i >> 2;
            #pragma unroll
            for (int mt = 0; mt < 4; mt++) {
                const int rl = mt * 16 + er;              // local row 0..63
                #pragma unroll
                for (int nt = 0; nt < 4; nt++) {
                    const int cl = warp_n * 32 + nt * 8 + ec;
                    const int col = n0 + cl;
                    if (t < 2) {
                        float2 p0 = *(const float2*)(smem + S_PXOFF + rl * S_PXROW + cl * 4);
                        float2 p1 = *(const float2*)(smem + S_PXOFF + (rl + 8) * S_PXROW + cl * 4);
                        const float* bp = (t == 0) ? bx : bh;
                        float b0 = bp[col], b1 = bp[col + 1];
                        s_acc[mt][nt][0] += (acc[mt][nt][0] + b0) * p0.x;
                        s_acc[mt][nt][1] += (acc[mt][nt][1] + b1) * p0.y;
                        s_acc[mt][nt][2] += (acc[mt][nt][2] + b0) * p1.x;
                        s_acc[mt][nt][3] += (acc[mt][nt][3] + b1) * p1.y;
                    } else {
                        float b0 = bb[col], b1 = bb[col + 1];
                        s_acc[mt][nt][0] += acc[mt][nt][0] + b0;
                        s_acc[mt][nt][1] += acc[mt][nt][1] + b1;
                        s_acc[mt][nt][2] += acc[mt][nt][2] + b0;
                        s_acc[mt][nt][3] += acc[mt][nt][3] + b1;
                    }
                    #pragma unroll
                    for (int c = 0; c < 4; c++) acc[mt][nt][c] = 0.0f;
                }
            }
        }
        __syncthreads();
    }

    #pragma unroll
    for (int mt = 0; mt < 4; mt++) {
        const int row = m0 + mt * 16 + er;
        #pragma unroll
        for (int nt = 0; nt < 4; nt++) {
            const int col = n0 + warp_n * 32 + nt * 8 + ec;
            *(float2*)(S + (size_t)row * FOURU + col) =
                make_float2(s_acc[mt][nt][0], s_acc[mt][nt][1]);
            *(float2*)(S + (size_t)(row + 8) * FOURU + col) =
                make_float2(s_acc[mt][nt][2], s_acc[mt][nt][3]);
        }
    }
}

// ---------------------------------------------------------------------------
// prep kernels
// ---------------------------------------------------------------------------
__global__ void concat_fp16(const float* __restrict__ inputs,
                            const float* __restrict__ main_h,
                            const float* __restrict__ hyper_h,
                            __half* __restrict__ Dh)
{
    int i4 = blockIdx.x * blockDim.x + threadIdx.x;
    if (i4 >= BB * KHYP / 4) return;
    int row = i4 / (KHYP / 4);
    int c4  = (i4 - row * (KHYP / 4)) * 4;
    const float* src;
    if (c4 < DD)            src = inputs  + (size_t)row * DD  + c4;
    else if (c4 < DD + UU)  src = main_h  + (size_t)row * UU  + (c4 - DD);
    else                    src = hyper_h + (size_t)row * HHU + (c4 - DD - UU);
    float4 v = *(const float4*)src;
    size_t o = (size_t)row * KHYP + c4;
    unsigned short hs[4];
    hs[0] = __half_as_ushort(__float2half_rn(v.x));
    hs[1] = __half_as_ushort(__float2half_rn(v.y));
    hs[2] = __half_as_ushort(__float2half_rn(v.z));
    hs[3] = __half_as_ushort(__float2half_rn(v.w));
    *(uint2*)(Dh + o) = make_uint2((uint32_t)hs[0] | ((uint32_t)hs[1] << 16),
                                   (uint32_t)hs[2] | ((uint32_t)hs[3] << 16));
}

__device__ __forceinline__ void trans_tile(const float* __restrict__ W,
                                           __half* __restrict__ Th,
                                           int N, int dstLd, int kOff,
                                           int n0, int k0)
{
    __shared__ float t[64][33];
    const int tx = threadIdx.x, ty = threadIdx.y;   // 32 x 8
    #pragma unroll
    for (int i = 0; i < 8; i++)
        t[ty + i * 8][tx] = W[(size_t)(k0 + ty + i * 8) * N + n0 + tx];
    __syncthreads();
    #pragma unroll
    for (int j = 0; j < 4; j++) {
        int n = ty + j * 8;
        float v0 = t[tx * 2][n], v1 = t[tx * 2 + 1][n];
        uint32_t pk = (uint32_t)__half_as_ushort(__float2half_rn(v0))
                    | ((uint32_t)__half_as_ushort(__float2half_rn(v1)) << 16);
        *(uint32_t*)(Th + (size_t)(n0 + n) * dstLd + kOff + k0 + tx * 2) = pk;
    }
}

__global__ void trans_d3(const float* __restrict__ w0, const float* __restrict__ w1,
                         const float* __restrict__ w2, __half* __restrict__ Tall)
{
    const float* W = (blockIdx.z == 0) ? w0 : (blockIdx.z == 1) ? w1 : w2;
    trans_tile(W, Tall + (size_t)blockIdx.z * FOURU * HHU, FOURU, HHU, 0,
               blockIdx.x * 32, blockIdx.y * 64);
}

__global__ void trans_kr(const float* __restrict__ kw, const float* __restrict__ rw,
                         __half* __restrict__ Tk, __half* __restrict__ Tr)
{
    const float* W = blockIdx.z ? rw : kw;
    __half* T = blockIdx.z ? Tr : Tk;
    trans_tile(W, T, FOURU, UU, 0, blockIdx.x * 32, blockIdx.y * 64);
}

__global__ void trans_hyp(const float* __restrict__ hk, const float* __restrict__ hr,
                          __half* __restrict__ T)
{
    if (blockIdx.z == 0) {
        trans_tile(hk, T, FOURHU, KHYP, 0, blockIdx.x * 32, blockIdx.y * 64);
    } else {
        if (blockIdx.y >= HHU / 64) return;
        trans_tile(hr, T, FOURHU, KHYP, DD + UU, blockIdx.x * 32, blockIdx.y * 64);
    }
}

// ---------------------------------------------------------------------------
// hyper LSTM pointwise (+ fp16 of hyper_out)
// ---------------------------------------------------------------------------
__global__ void hyper_pointwise(const float* __restrict__ z,
                                const float* __restrict__ hyper_c,
                                float* __restrict__ hyper_out,
                                float* __restrict__ hyper_c_new,
                                __half* __restrict__ hoh)
{
    int idx = blockIdx.x * blockDim.x + threadIdx.x;
    if (idx >= BB * HHU) return;
    int b = idx / HHU;
    int u = idx - b * HHU;
    const float* zr = z + (size_t)b * FOURHU;
    float hi = zr[u];
    float hf = zr[HHU + u];
    float hg = zr[2 * HHU + u];
    float ho = zr[3 * HHU + u];
    float c = sigf(hf) * hyper_c[idx] + sigf(hi) * tanhf(hg);
    hyper_c_new[idx] = c;
    float out = sigf(ho) * tanhf(c);
    hyper_out[idx] = out;
    hoh[idx] = __float2half_rn(out);
}

// ---------------------------------------------------------------------------
// LN epilogue
// ---------------------------------------------------------------------------
__device__ __forceinline__ void block_reduce2(float& a, float& b, float* sm)
{
    __syncthreads();
    #pragma unroll
    for (int o = 16; o > 0; o >>= 1) {
        a += __shfl_down_sync(0xffffffffu, a, o);
        b += __shfl_down_sync(0xffffffffu, b, o);
    }
    int w = threadIdx.x >> 5, l = threadIdx.x & 31;
    if (l == 0) { sm[w] = a; sm[32 + w] = b; }
    __syncthreads();
    if (w == 0) {
        int nw = blockDim.x >> 5;
        a = (l < nw) ? sm[l] : 0.0f;
        b = (l < nw) ? sm[32 + l] : 0.0f;
        #pragma unroll
        for (int o = 16; o > 0; o >>= 1) {
            a += __shfl_down_sync(0xffffffffu, a, o);
            b += __shfl_down_sync(0xffffffffu, b, o);
        }
        if (l == 0) { sm[0] = a; sm[32] = b; }
    }
    __syncthreads();
    a = sm[0];
    b = sm[32];
}

__global__ __launch_bounds__(512)
void main_epilogue(const float* __restrict__ S, const float* __restrict__ main_c,
                   float* __restrict__ out_h, float* __restrict__ out_c)
{
    __shared__ float sm[64];
    const int b = blockIdx.x;
    const int t = threadIdx.x;
    const size_t b4 = (size_t)b * FOURU;

    float s[8];
    float sum = 0.0f, sq = 0.0f;
    #pragma unroll
    for (int r = 0; r < 8; r++) {
        float v = S[b4 + t + r * 512];
        s[r] = v;
        sum += v;
        sq = fmaf(v, v, sq);
    }
    block_reduce2(sum, sq, sm);
    float mean = sum * (1.0f / 4096.0f);
    float var = sq * (1.0f / 4096.0f) - mean * mean;
    float inv = rsqrtf(var + 1e-3f);

    float i0 = (s[0] - mean) * inv, i1 = (s[1] - mean) * inv;
    float f0 = (s[2] - mean) * inv, f1 = (s[3] - mean) * inv;
    float g0 = (s[4] - mean) * inv, g1 = (s[5] - mean) * inv;
    float o0 = (s[6] - mean) * inv, o1 = (s[7] - mean) * inv;

    const size_t cb = (size_t)b * UU;
    float c0 = sigf(f0) * main_c[cb + t]       + sigf(i0) * tanhf(g0);
    float c1 = sigf(f1) * main_c[cb + t + 512] + sigf(i1) * tanhf(g1);

    float sum2 = c0 + c1;
    float sq2 = fmaf(c0, c0, c1 * c1);
    block_reduce2(sum2, sq2, sm);
    float mean2 = sum2 * (1.0f / 1024.0f);
    float var2 = sq2 * (1.0f / 1024.0f) - mean2 * mean2;
    float inv2 = rsqrtf(var2 + 1e-3f);

    float h0 = sigf(o0) * tanhf((c0 - mean2) * inv2);
    float h1 = sigf(o1) * tanhf((c1 - mean2) * inv2);

    out_c[cb + t] = c0;
    out_c[cb + t + 512] = c1;
    out_h[cb + t] = h0;
    out_h[cb + t + 512] = h1;
}

// ---------------------------------------------------------------------------
// launch
// ---------------------------------------------------------------------------
static cudaStream_t make_stream() {
    cudaStream_t s;
    cudaStreamCreateWithFlags(&s, cudaStreamNonBlocking);
    return s;
}
static cudaEvent_t make_event() {
    cudaEvent_t e;
    cudaEventCreateWithFlags(&e, cudaEventDisableTiming);
    return e;
}

extern "C" void kernel_launch(void* const* d_in, const int* in_sizes, int n_in,
                              void* d_out, int out_size)
{
    const float* inputs       = (const float*)d_in[0];
    const float* main_h       = (const float*)d_in[1];
    const float* main_c       = (const float*)d_in[2];
    const float* hyper_h      = (const float*)d_in[3];
    const float* hyper_c      = (const float*)d_in[4];
    const float* kernel_w     = (const float*)d_in[5];
    const float* rec_w        = (const float*)d_in[6];
    const float* bias         = (const float*)d_in[7];
    const float* hyper_kernel = (const float*)d_in[8];
    const float* hyper_rec    = (const float*)d_in[9];
    const float* hyper_bias   = (const float*)d_in[10];
    const float* dx_w         = (const float*)d_in[11];
    const float* dx_b         = (const float*)d_in[12];
    const float* dh_w         = (const float*)d_in[13];
    const float* dh_b         = (const float*)d_in[14];
    const float* db_w         = (const float*)d_in[15];
    const float* db_b         = (const float*)d_in[16];

    float* out = (float*)d_out;
    float* out_h  = out;
    float* out_c  = out + (size_t)BB * UU;
    float* out_ho = out + (size_t)2 * BB * UU;
    float* out_hc = out_ho + (size_t)BB * HHU;

    float *z, *s, *px, *phv;
    cudaGetSymbolAddress((void**)&z,   g_z);
    cudaGetSymbolAddress((void**)&s,   g_s);
    cudaGetSymbolAddress((void**)&px,  g_px);
    cudaGetSymbolAddress((void**)&phv, g_ph);

    __half *ahyp, *aho, *wthyp, *wtall, *wtk, *wtr;
    cudaGetSymbolAddress((void**)&ahyp,  g_ahyp);
    cudaGetSymbolAddress((void**)&aho,   g_aho);
    cudaGetSymbolAddress((void**)&wthyp, g_wthyp);
    cudaGetSymbolAddress((void**)&wtall, g_wtall);
    cudaGetSymbolAddress((void**)&wtk,   g_wtk);
    cudaGetSymbolAddress((void**)&wtr,   g_wtr);

    cudaFuncSetAttribute(gemm_all, cudaFuncAttributeMaxDynamicSharedMemorySize, G_SMEM);
    cudaFuncSetAttribute(gemm_s,   cudaFuncAttributeMaxDynamicSharedMemorySize, S_SMEM);

    // One-time resources (created outside capture on first call; reused after).
    static cudaStream_t sB = make_stream();
    static cudaStream_t sC = make_stream();
    static cudaEvent_t evRoot  = make_event();
    static cudaEvent_t evHypW  = make_event();
    static cudaEvent_t evD3    = make_event();
    static cudaEvent_t evKR    = make_event();

    dim3 tb(32, 8);

    // ---- fork side streams at graph root ----
    cudaEventRecord(evRoot, 0);
    cudaStreamWaitEvent(sB, evRoot, 0);
    cudaStreamWaitEvent(sC, evRoot, 0);

    // three concurrent prep branches
    concat_fp16<<<(BB * KHYP / 4 + 255) / 256, 256>>>(inputs, main_h, hyper_h, ahyp);

    trans_kr<<<dim3(FOURU/32, UU/64, 2), tb, 0, sC>>>(kernel_w, rec_w, wtk, wtr);
    cudaEventRecord(evKR, sC);

    trans_hyp<<<dim3(FOURHU/32, (DD+UU)/64, 2), tb, 0, sB>>>(hyper_kernel, hyper_rec, wthyp);
    cudaEventRecord(evHypW, sB);
    trans_d3 <<<dim3(FOURU/32, HHU/64, 3), tb, 0, sB>>>(dx_w, dh_w, db_w, wtall);
    cudaEventRecord(evD3, sB);

    // ---- one combined GEMM launch (hyper tiles first) ----
    cudaStreamWaitEvent(0, evKR, 0);
    cudaStreamWaitEvent(0, evHypW, 0);
    gemm_all<<<576, 256, G_SMEM>>>(ahyp, wtk, wtr, wthyp, bias, hyper_bias, px, phv, z);

    // ---- hyper pointwise ----
    hyper_pointwise<<<(BB * HHU + 255) / 256, 256>>>(z, hyper_c, out_ho, out_hc, aho);

    // ---- fused d-GEMM + gate combine -> s (64-row tiles, 2 CTAs/SM) ----
    cudaStreamWaitEvent(0, evD3, 0);
    gemm_s<<<dim3(FOURU/128, BB/64), 128, S_SMEM>>>(
        aho, wtall, dx_b, dh_b, db_b, px, phv, s);

    main_epilogue<<<BB, 512>>>(s, main_c, out_h, out_c);
}

// round 16
// speedup vs baseline: 1.4119x; 1.0160x over previous
#include <cuda_runtime.h>
#include <cuda_fp16.h>
#include <math.h>
#include <cstdint>

#define BB 2048
#define DD 1024
#define UU 1024
#define HHU 256
#define FOURU (4*UU)     // 4096
#define FOURHU (4*HHU)   // 1024
#define KHYP (DD+UU+HHU) // 2304
#define N3 (3*FOURU)     // 12288

// ---------------------------------------------------------------------------
// scratch (static device arrays; no allocation allowed)
// ---------------------------------------------------------------------------
__device__ float  g_z [BB * FOURHU];
__device__ float  g_s [BB * FOURU];    // fused gate pre-activations
__device__ __half g_px[BB * FOURU];    // fp16 multipliers
__device__ __half g_ph[BB * FOURU];

// fp16 activations
__device__ __half g_ahyp[BB * KHYP];   // fp16 of [inputs|main_h|hyper_h]
__device__ __half g_aho [BB * HHU];    // fp16 of hyper_out
// transposed fp16 weights ([N, K] row-major, k-contiguous)
__device__ __half g_wthyp[FOURHU * KHYP];
__device__ __half g_wtall[N3 * HHU];   // dx_w^T | dh_w^T | db_w^T stacked on N
__device__ __half g_wtk[FOURU * UU];
__device__ __half g_wtr[FOURU * UU];

__device__ __forceinline__ float sigf(float x) { return 1.0f / (1.0f + expf(-x)); }

__device__ __forceinline__ uint32_t smem_u32(const void* p) {
    uint32_t a;
    asm("{ .reg .u64 t; cvta.to.shared.u64 t, %1; cvt.u32.u64 %0, t; }" : "=r"(a) : "l"(p));
    return a;
}
__device__ __forceinline__ void cpa16(uint32_t dst, const void* src) {
    asm volatile("cp.async.cg.shared.global [%0], [%1], 16;" :: "r"(dst), "l"(src));
}
#define CP_COMMIT() asm volatile("cp.async.commit_group;" ::: "memory")
#define CP_WAIT(n)  asm volatile("cp.async.wait_group %0;" :: "n"(n) : "memory")

__device__ __forceinline__ void ldsm4(uint32_t* r, uint32_t addr) {
    asm volatile("ldmatrix.sync.aligned.m8n8.x4.shared.b16 {%0,%1,%2,%3}, [%4];"
                 : "=r"(r[0]), "=r"(r[1]), "=r"(r[2]), "=r"(r[3]) : "r"(addr));
}
__device__ __forceinline__ void mma_f16(float* c, const uint32_t* a, uint32_t b0, uint32_t b1) {
    asm volatile("mma.sync.aligned.m16n8k16.row.col.f32.f16.f16.f32 "
                 "{%0,%1,%2,%3}, {%4,%5,%6,%7}, {%8,%9}, {%0,%1,%2,%3};"
                 : "+f"(c[0]), "+f"(c[1]), "+f"(c[2]), "+f"(c[3])
                 : "r"(a[0]), "r"(a[1]), "r"(a[2]), "r"(a[3]), "r"(b0), "r"(b1));
}

#define SROW 144

// ---------------------------------------------------------------------------
// 1-term GEMM core: C[M,N] = A[M,K] @ W[N,K]^T (+bias); OT = float or __half.
// CTA tile 128 x 256; 8 warps 2(m) x 4(n); warp tile 64x64; BK=64;
// 3-stage cp.async pipeline; 256 threads.
// ---------------------------------------------------------------------------
#define G_ABYTES (128 * SROW)                 // 18432
#define G_SSZ    ((128 + 256) * SROW)         // 55296
#define G_SMEM   (3 * G_SSZ)                  // 165888

template<typename OT>
__device__ __forceinline__
void gemm_core4(const __half* __restrict__ Ah, int lda,
                const __half* __restrict__ Wh, int ldw,
                const float* __restrict__ bias, OT* __restrict__ C,
                int N, int K, char* smem, int bx, int by)
{
    const uint32_t sb = smem_u32(smem);
    const int tid  = threadIdx.x;
    const int lane = tid & 31;
    const int wid  = tid >> 5;
    const int warp_m = wid & 1;
    const int warp_n = wid >> 1;
    const int m0 = by * 128;
    const int n0 = bx * 256;

    const __half* pAh = Ah + (size_t)m0 * lda;
    const __half* pWh = Wh + (size_t)n0 * ldw;

    float acc[4][8][4];
    #pragma unroll
    for (int a = 0; a < 4; a++)
        #pragma unroll
        for (int b = 0; b < 8; b++)
            #pragma unroll
            for (int c = 0; c < 4; c++) acc[a][b][c] = 0.0f;

    const uint32_t fr  = lane & 15;
    const uint32_t fcb = (lane >> 4) * 16;
    const int lr = tid >> 3;        // 0..31
    const int lc = tid & 7;
    const int nch = K / 64;

    auto load_stage = [&](uint32_t base, int k0) {
        #pragma unroll
        for (int i = 0; i < 4; i++) {
            int row = lr + i * 32;
            cpa16(base + row * SROW + lc * 16, pAh + (size_t)row * lda + k0 + lc * 8);
        }
        #pragma unroll
        for (int i = 0; i < 8; i++) {
            int row = lr + i * 32;
            cpa16(base + G_ABYTES + row * SROW + lc * 16, pWh + (size_t)row * ldw + k0 + lc * 8);
        }
    };

    load_stage(sb, 0);
    CP_COMMIT();
    load_stage(sb + G_SSZ, 64);
    CP_COMMIT();

    int buf = 0;
    int nbuf = 2;

    for (int kc = 0; kc < nch; kc++) {
        if (kc + 2 < nch) {
            load_stage(sb + nbuf * G_SSZ, (kc + 2) * 64);
            CP_COMMIT();
            nbuf = (nbuf == 2) ? 0 : nbuf + 1;
            CP_WAIT(2);
        } else if (kc + 1 < nch) {
            CP_WAIT(1);
        } else {
            CP_WAIT(0);
        }
        __syncthreads();

        const uint32_t stg = sb + buf * G_SSZ;
        buf = (buf == 2) ? 0 : buf + 1;
        #pragma unroll
        for (int s = 0; s < 4; s++) {
            const uint32_t kb = s * 32 + fcb;
            uint32_t ah[4][4];
            #pragma unroll
            for (int mt = 0; mt < 4; mt++)
                ldsm4(ah[mt], stg + (warp_m * 64 + mt * 16 + fr) * SROW + kb);
            #pragma unroll
            for (int np = 0; np < 4; np++) {
                uint32_t w[4];
                ldsm4(w, stg + G_ABYTES + (warp_n * 64 + np * 16 + fr) * SROW + kb);
                #pragma unroll
                for (int mt = 0; mt < 4; mt++) {
                    mma_f16(acc[mt][2*np],   ah[mt], w[0], w[2]);
                    mma_f16(acc[mt][2*np+1], ah[mt], w[1], w[3]);
                }
            }
        }
        __syncthreads();
    }

    const int er = lane >> 2;
    const int ec = (lane & 3) * 2;
    #pragma unroll
    for (int mt = 0; mt < 4; mt++) {
        const int row = m0 + warp_m * 64 + mt * 16 + er;
        #pragma unroll
        for (int nt = 0; nt < 8; nt++) {
            const int col = n0 + warp_n * 64 + nt * 8 + ec;
            float b0 = 0.f, b1 = 0.f;
            if (bias) { b0 = bias[col]; b1 = bias[col + 1]; }
            float v00 = acc[mt][nt][0] + b0, v01 = acc[mt][nt][1] + b1;
            float v10 = acc[mt][nt][2] + b0, v11 = acc[mt][nt][3] + b1;
            if constexpr (sizeof(OT) == 4) {
                *(float2*)((float*)C + (size_t)row * N + col) = make_float2(v00, v01);
                *(float2*)((float*)C + (size_t)(row + 8) * N + col) = make_float2(v10, v11);
            } else {
                *(__half2*)((__half*)C + (size_t)row * N + col) = __floats2half2_rn(v00, v01);
                *(__half2*)((__half*)C + (size_t)(row + 8) * N + col) = __floats2half2_rn(v10, v11);
            }
        }
    }
}

// ---------------------------------------------------------------------------
// gemm_all: hyper + px + ph in one flat-grid launch.
// blocks [0,64): hyper (N=1024, K=2304, fp32 z out) -- scheduled FIRST
// blocks [64,320): px (N=4096, K=1024, fp16 out)
// blocks [320,576): ph (N=4096, K=1024, fp16 out)
// ---------------------------------------------------------------------------
__global__ __launch_bounds__(256, 1)
void gemm_all(const __half* __restrict__ ahyp,
              const __half* __restrict__ wtk, const __half* __restrict__ wtr,
              const __half* __restrict__ wthyp,
              const float* __restrict__ bias, const float* __restrict__ hyper_bias,
              __half* __restrict__ px, __half* __restrict__ ph, float* __restrict__ z)
{
    extern __shared__ char smem[];
    const int b = blockIdx.x;
    if (b < 64) {
        gemm_core4<float>(ahyp, KHYP, wthyp, KHYP, hyper_bias, z, FOURHU, KHYP,
                          smem, b & 3, b >> 2);
    } else if (b < 320) {
        const int i = b - 64;
        gemm_core4<__half>(ahyp, KHYP, wtk, UU, bias, px, FOURU, UU,
                           smem, i & 15, i >> 4);
    } else {
        const int i = b - 320;
        gemm_core4<__half>(ahyp + DD, KHYP, wtr, UU, nullptr, ph, FOURU, UU,
                           smem, i & 15, i >> 4);
    }
}

// ---------------------------------------------------------------------------
// gemm_s: fused d_x/d_h/d_b GEMM + gate combine, fp16 px/ph via smem prefetch.
// CTA tile 64(m) x 128(n); 128 threads; 4 warps 1(m) x 4(n); warp tile 64x32.
// ~91 KB smem -> 2 CTAs/SM.
// ---------------------------------------------------------------------------
#define S_ATILE  (64 * SROW)               // 9216
#define S_WTILE  (128 * SROW)              // 18432
#define S_WOFF   (4 * S_ATILE)             // 36864
#define S_PXOFF  (S_WOFF + 2 * S_WTILE)    // 73728
#define S_PXROW  272                        // 128 halfs (256B) + 16B pad
#define S_SMEM   (S_PXOFF + 64 * S_PXROW)  // 91136

__global__ __launch_bounds__(128, 2)
void gemm_s(const __half* __restrict__ A,          // aho [2048,256]
            const __half* __restrict__ Wall,       // [12288,256]
            const float* __restrict__ bx, const float* __restrict__ bh,
            const float* __restrict__ bb,
            const __half* __restrict__ px, const __half* __restrict__ ph,
            float* __restrict__ S)
{
    extern __shared__ char smem[];
    const uint32_t sb = smem_u32(smem);
    const int tid  = threadIdx.x;
    const int lane = tid & 31;
    const int warp_n = tid >> 5;            // 0..3
    const int m0 = blockIdx.y * 64;
    const int n0 = blockIdx.x * 128;

    const __half* pA = A + (size_t)m0 * HHU;

    const uint32_t fr  = lane & 15;
    const uint32_t fcb = (lane >> 4) * 16;
    const int lr = tid >> 3;                // 0..15
    const int lc = tid & 7;

    // load full A (4 chunks of 64x64 halfs)
    #pragma unroll
    for (int c = 0; c < 4; c++)
        #pragma unroll
        for (int i = 0; i < 4; i++) {
            int row = lr + i * 16;
            cpa16(sb + c * S_ATILE + row * SROW + lc * 16,
                  pA + (size_t)row * HHU + c * 64 + lc * 8);
        }
    auto load_w = [&](int t, int kc, int buf) {
        const __half* pW = Wall + (size_t)t * FOURU * HHU + (size_t)n0 * HHU;
        #pragma unroll
        for (int i = 0; i < 8; i++) {
            int row = lr + i * 16;
            cpa16(sb + S_WOFF + buf * S_WTILE + row * SROW + lc * 16,
                  pW + (size_t)row * HHU + kc * 64 + lc * 8);
        }
    };
    // prefetch a 64x128 fp16 tile of P (16KB): 1024 16B chunks, 8 iters
    auto load_p = [&](const __half* __restrict__ P) {
        #pragma unroll
        for (int it = 0; it < 8; it++) {
            int idx = tid + it * 128;       // 0..1023
            int row = idx >> 4;             // 0..63
            int c16 = idx & 15;             // 0..15 (8 halfs each)
            cpa16(sb + S_PXOFF + row * S_PXROW + c16 * 16,
                  P + (size_t)(m0 + row) * FOURU + n0 + c16 * 8);
        }
    };

    load_w(0, 0, 0);
    CP_COMMIT();

    float s_acc[4][4][4];
    #pragma unroll
    for (int a = 0; a < 4; a++)
        #pragma unroll
        for (int b = 0; b < 4; b++)
            #pragma unroll
            for (int c = 0; c < 4; c++) s_acc[a][b][c] = 0.0f;

    float acc[4][4][4];
    #pragma unroll
    for (int a = 0; a < 4; a++)
        #pragma unroll
        for (int b = 0; b < 4; b++)
            #pragma unroll
            for (int c = 0; c < 4; c++) acc[a][b][c] = 0.0f;

    const int er = lane >> 2;
    const int ec = (lane & 3) * 2;

    for (int i = 0; i < 12; i++) {
        const int kc = i & 3;
        if (i + 1 < 12) {
            load_w((i + 1) >> 2, (i + 1) & 3, (i + 1) & 1);
            if (i == 0) load_p(px);   // used end of iter 3
            if (i == 4) load_p(ph);   // same buffer; used end of iter 7
            CP_COMMIT();
            CP_WAIT(1);
        } else {
            CP_WAIT(0);
        }
        __syncthreads();

        const uint32_t wb = sb + S_WOFF + (i & 1) * S_WTILE;
        const uint32_t ab = sb + kc * S_ATILE;
        #pragma unroll
        for (int s = 0; s < 4; s++) {
            const uint32_t kb = s * 32 + fcb;
            uint32_t ah[4][4];
            #pragma unroll
            for (int mt = 0; mt < 4; mt++)
                ldsm4(ah[mt], ab + (mt * 16 + fr) * SROW + kb);
            #pragma unroll
            for (int np = 0; np < 2; np++) {
                uint32_t w[4];
                ldsm4(w, wb + (warp_n * 32 + np * 16 + fr) * SROW + kb);
                #pragma unroll
                for (int mt = 0; mt < 4; mt++) {
                    mma_f16(acc[mt][2*np],   ah[mt], w[0], w[2]);
                    mma_f16(acc[mt][2*np+1], ah[mt], w[1], w[3]);
                }
            }
        }

        if (kc == 3) {
            const int t = i >> 2;
            #pragma unroll
            for (int mt = 0; mt < 4; mt++) {
                const int rl = mt * 16 + er;              // local row 0..63
                #pragma unroll
                for (int nt = 0; nt < 4; nt++) {
                    const int cl = warp_n * 32 + nt * 8 + ec;
                    const int col = n0 + cl;
                    if (t < 2) {
                        float2 p0 = __half22float2(
                            *(const __half2*)(smem + S_PXOFF + rl * S_PXROW + cl * 2));
                        float2 p1 = __half22float2(
                            *(const __half2*)(smem + S_PXOFF + (rl + 8) * S_PXROW + cl * 2));
                        const float* bp = (t == 0) ? bx : bh;
                        float b0 = bp[col], b1 = bp[col + 1];
                        s_acc[mt][nt][0] += (acc[mt][nt][0] + b0) * p0.x;
                        s_acc[mt][nt][1] += (acc[mt][nt][1] + b1) * p0.y;
                        s_acc[mt][nt][2] += (acc[mt][nt][2] + b0) * p1.x;
                        s_acc[mt][nt][3] += (acc[mt][nt][3] + b1) * p1.y;
                    } else {
                        float b0 = bb[col], b1 = bb[col + 1];
                        s_acc[mt][nt][0] += acc[mt][nt][0] + b0;
                        s_acc[mt][nt][1] += acc[mt][nt][1] + b1;
                        s_acc[mt][nt][2] += acc[mt][nt][2] + b0;
                        s_acc[mt][nt][3] += acc[mt][nt][3] + b1;
                    }
                    #pragma unroll
                    for (int c = 0; c < 4; c++) acc[mt][nt][c] = 0.0f;
                }
            }
        }
        __syncthreads();
    }

    #pragma unroll
    for (int mt = 0; mt < 4; mt++) {
        const int row = m0 + mt * 16 + er;
        #pragma unroll
        for (int nt = 0; nt < 4; nt++) {
            const int col = n0 + warp_n * 32 + nt * 8 + ec;
            *(float2*)(S + (size_t)row * FOURU + col) =
                make_float2(s_acc[mt][nt][0], s_acc[mt][nt][1]);
            *(float2*)(S + (size_t)(row + 8) * FOURU + col) =
                make_float2(s_acc[mt][nt][2], s_acc[mt][nt][3]);
        }
    }
}

// ---------------------------------------------------------------------------
// prep kernels
// ---------------------------------------------------------------------------
__global__ void concat_fp16(const float* __restrict__ inputs,
                            const float* __restrict__ main_h,
                            const float* __restrict__ hyper_h,
                            __half* __restrict__ Dh)
{
    int i4 = blockIdx.x * blockDim.x + threadIdx.x;
    if (i4 >= BB * KHYP / 4) return;
    int row = i4 / (KHYP / 4);
    int c4  = (i4 - row * (KHYP / 4)) * 4;
    const float* src;
    if (c4 < DD)            src = inputs  + (size_t)row * DD  + c4;
    else if (c4 < DD + UU)  src = main_h  + (size_t)row * UU  + (c4 - DD);
    else                    src = hyper_h + (size_t)row * HHU + (c4 - DD - UU);
    float4 v = *(const float4*)src;
    size_t o = (size_t)row * KHYP + c4;
    unsigned short hs[4];
    hs[0] = __half_as_ushort(__float2half_rn(v.x));
    hs[1] = __half_as_ushort(__float2half_rn(v.y));
    hs[2] = __half_as_ushort(__float2half_rn(v.z));
    hs[3] = __half_as_ushort(__float2half_rn(v.w));
    *(uint2*)(Dh + o) = make_uint2((uint32_t)hs[0] | ((uint32_t)hs[1] << 16),
                                   (uint32_t)hs[2] | ((uint32_t)hs[3] << 16));
}

__device__ __forceinline__ void trans_tile(const float* __restrict__ W,
                                           __half* __restrict__ Th,
                                           int N, int dstLd, int kOff,
                                           int n0, int k0)
{
    __shared__ float t[64][33];
    const int tx = threadIdx.x, ty = threadIdx.y;   // 32 x 8
    #pragma unroll
    for (int i = 0; i < 8; i++)
        t[ty + i * 8][tx] = W[(size_t)(k0 + ty + i * 8) * N + n0 + tx];
    __syncthreads();
    #pragma unroll
    for (int j = 0; j < 4; j++) {
        int n = ty + j * 8;
        float v0 = t[tx * 2][n], v1 = t[tx * 2 + 1][n];
        uint32_t pk = (uint32_t)__half_as_ushort(__float2half_rn(v0))
                    | ((uint32_t)__half_as_ushort(__float2half_rn(v1)) << 16);
        *(uint32_t*)(Th + (size_t)(n0 + n) * dstLd + kOff + k0 + tx * 2) = pk;
    }
}

__global__ void trans_d3(const float* __restrict__ w0, const float* __restrict__ w1,
                         const float* __restrict__ w2, __half* __restrict__ Tall)
{
    const float* W = (blockIdx.z == 0) ? w0 : (blockIdx.z == 1) ? w1 : w2;
    trans_tile(W, Tall + (size_t)blockIdx.z * FOURU * HHU, FOURU, HHU, 0,
               blockIdx.x * 32, blockIdx.y * 64);
}

__global__ void trans_kr(const float* __restrict__ kw, const float* __restrict__ rw,
                         __half* __restrict__ Tk, __half* __restrict__ Tr)
{
    const float* W = blockIdx.z ? rw : kw;
    __half* T = blockIdx.z ? Tr : Tk;
    trans_tile(W, T, FOURU, UU, 0, blockIdx.x * 32, blockIdx.y * 64);
}

__global__ void trans_hyp(const float* __restrict__ hk, const float* __restrict__ hr,
                          __half* __restrict__ T)
{
    if (blockIdx.z == 0) {
        trans_tile(hk, T, FOURHU, KHYP, 0, blockIdx.x * 32, blockIdx.y * 64);
    } else {
        if (blockIdx.y >= HHU / 64) return;
        trans_tile(hr, T, FOURHU, KHYP, DD + UU, blockIdx.x * 32, blockIdx.y * 64);
    }
}

// ---------------------------------------------------------------------------
// hyper LSTM pointwise (+ fp16 of hyper_out)
// ---------------------------------------------------------------------------
__global__ void hyper_pointwise(const float* __restrict__ z,
                                const float* __restrict__ hyper_c,
                                float* __restrict__ hyper_out,
                                float* __restrict__ hyper_c_new,
                                __half* __restrict__ hoh)
{
    int idx = blockIdx.x * blockDim.x + threadIdx.x;
    if (idx >= BB * HHU) return;
    int b = idx / HHU;
    int u = idx - b * HHU;
    const float* zr = z + (size_t)b * FOURHU;
    float hi = zr[u];
    float hf = zr[HHU + u];
    float hg = zr[2 * HHU + u];
    float ho = zr[3 * HHU + u];
    float c = sigf(hf) * hyper_c[idx] + sigf(hi) * tanhf(hg);
    hyper_c_new[idx] = c;
    float out = sigf(ho) * tanhf(c);
    hyper_out[idx] = out;
    hoh[idx] = __float2half_rn(out);
}

// ---------------------------------------------------------------------------
// LN epilogue
// ---------------------------------------------------------------------------
__device__ __forceinline__ void block_reduce2(float& a, float& b, float* sm)
{
    __syncthreads();
    #pragma unroll
    for (int o = 16; o > 0; o >>= 1) {
        a += __shfl_down_sync(0xffffffffu, a, o);
        b += __shfl_down_sync(0xffffffffu, b, o);
    }
    int w = threadIdx.x >> 5, l = threadIdx.x & 31;
    if (l == 0) { sm[w] = a; sm[32 + w] = b; }
    __syncthreads();
    if (w == 0) {
        int nw = blockDim.x >> 5;
        a = (l < nw) ? sm[l] : 0.0f;
        b = (l < nw) ? sm[32 + l] : 0.0f;
        #pragma unroll
        for (int o = 16; o > 0; o >>= 1) {
            a += __shfl_down_sync(0xffffffffu, a, o);
            b += __shfl_down_sync(0xffffffffu, b, o);
        }
        if (l == 0) { sm[0] = a; sm[32] = b; }
    }
    __syncthreads();
    a = sm[0];
    b = sm[32];
}

__global__ __launch_bounds__(512)
void main_epilogue(const float* __restrict__ S, const float* __restrict__ main_c,
                   float* __restrict__ out_h, float* __restrict__ out_c)
{
    __shared__ float sm[64];
    const int b = blockIdx.x;
    const int t = threadIdx.x;
    const size_t b4 = (size_t)b * FOURU;

    float s[8];
    float sum = 0.0f, sq = 0.0f;
    #pragma unroll
    for (int r = 0; r < 8; r++) {
        float v = S[b4 + t + r * 512];
        s[r] = v;
        sum += v;
        sq = fmaf(v, v, sq);
    }
    block_reduce2(sum, sq, sm);
    float mean = sum * (1.0f / 4096.0f);
    float var = sq * (1.0f / 4096.0f) - mean * mean;
    float inv = rsqrtf(var + 1e-3f);

    float i0 = (s[0] - mean) * inv, i1 = (s[1] - mean) * inv;
    float f0 = (s[2] - mean) * inv, f1 = (s[3] - mean) * inv;
    float g0 = (s[4] - mean) * inv, g1 = (s[5] - mean) * inv;
    float o0 = (s[6] - mean) * inv, o1 = (s[7] - mean) * inv;

    const size_t cb = (size_t)b * UU;
    float c0 = sigf(f0) * main_c[cb + t]       + sigf(i0) * tanhf(g0);
    float c1 = sigf(f1) * main_c[cb + t + 512] + sigf(i1) * tanhf(g1);

    float sum2 = c0 + c1;
    float sq2 = fmaf(c0, c0, c1 * c1);
    block_reduce2(sum2, sq2, sm);
    float mean2 = sum2 * (1.0f / 1024.0f);
    float var2 = sq2 * (1.0f / 1024.0f) - mean2 * mean2;
    float inv2 = rsqrtf(var2 + 1e-3f);

    float h0 = sigf(o0) * tanhf((c0 - mean2) * inv2);
    float h1 = sigf(o1) * tanhf((c1 - mean2) * inv2);

    out_c[cb + t] = c0;
    out_c[cb + t + 512] = c1;
    out_h[cb + t] = h0;
    out_h[cb + t + 512] = h1;
}

// ---------------------------------------------------------------------------
// launch
// ---------------------------------------------------------------------------
static cudaStream_t make_stream() {
    cudaStream_t s;
    cudaStreamCreateWithFlags(&s, cudaStreamNonBlocking);
    return s;
}
static cudaEvent_t make_event() {
    cudaEvent_t e;
    cudaEventCreateWithFlags(&e, cudaEventDisableTiming);
    return e;
}

extern "C" void kernel_launch(void* const* d_in, const int* in_sizes, int n_in,
                              void* d_out, int out_size)
{
    const float* inputs       = (const float*)d_in[0];
    const float* main_h       = (const float*)d_in[1];
    const float* main_c       = (const float*)d_in[2];
    const float* hyper_h      = (const float*)d_in[3];
    const float* hyper_c      = (const float*)d_in[4];
    const float* kernel_w     = (const float*)d_in[5];
    const float* rec_w        = (const float*)d_in[6];
    const float* bias         = (const float*)d_in[7];
    const float* hyper_kernel = (const float*)d_in[8];
    const float* hyper_rec    = (const float*)d_in[9];
    const float* hyper_bias   = (const float*)d_in[10];
    const float* dx_w         = (const float*)d_in[11];
    const float* dx_b         = (const float*)d_in[12];
    const float* dh_w         = (const float*)d_in[13];
    const float* dh_b         = (const float*)d_in[14];
    const float* db_w         = (const float*)d_in[15];
    const float* db_b         = (const float*)d_in[16];

    float* out = (float*)d_out;
    float* out_h  = out;
    float* out_c  = out + (size_t)BB * UU;
    float* out_ho = out + (size_t)2 * BB * UU;
    float* out_hc = out_ho + (size_t)BB * HHU;

    float *z, *s;
    __half *px, *phv;
    cudaGetSymbolAddress((void**)&z,   g_z);
    cudaGetSymbolAddress((void**)&s,   g_s);
    cudaGetSymbolAddress((void**)&px,  g_px);
    cudaGetSymbolAddress((void**)&phv, g_ph);

    __half *ahyp, *aho, *wthyp, *wtall, *wtk, *wtr;
    cudaGetSymbolAddress((void**)&ahyp,  g_ahyp);
    cudaGetSymbolAddress((void**)&aho,   g_aho);
    cudaGetSymbolAddress((void**)&wthyp, g_wthyp);
    cudaGetSymbolAddress((void**)&wtall, g_wtall);
    cudaGetSymbolAddress((void**)&wtk,   g_wtk);
    cudaGetSymbolAddress((void**)&wtr,   g_wtr);

    cudaFuncSetAttribute(gemm_all, cudaFuncAttributeMaxDynamicSharedMemorySize, G_SMEM);
    cudaFuncSetAttribute(gemm_s,   cudaFuncAttributeMaxDynamicSharedMemorySize, S_SMEM);

    // One-time resources (created outside capture on first call; reused after).
    static cudaStream_t sB = make_stream();
    static cudaStream_t sC = make_stream();
    static cudaEvent_t evRoot  = make_event();
    static cudaEvent_t evHypW  = make_event();
    static cudaEvent_t evD3    = make_event();
    static cudaEvent_t evKR    = make_event();

    dim3 tb(32, 8);

    // ---- fork side streams at graph root ----
    cudaEventRecord(evRoot, 0);
    cudaStreamWaitEvent(sB, evRoot, 0);
    cudaStreamWaitEvent(sC, evRoot, 0);

    // three concurrent prep branches
    concat_fp16<<<(BB * KHYP / 4 + 255) / 256, 256>>>(inputs, main_h, hyper_h, ahyp);

    trans_kr<<<dim3(FOURU/32, UU/64, 2), tb, 0, sC>>>(kernel_w, rec_w, wtk, wtr);
    cudaEventRecord(evKR, sC);

    trans_hyp<<<dim3(FOURHU/32, (DD+UU)/64, 2), tb, 0, sB>>>(hyper_kernel, hyper_rec, wthyp);
    cudaEventRecord(evHypW, sB);
    trans_d3 <<<dim3(FOURU/32, HHU/64, 3), tb, 0, sB>>>(dx_w, dh_w, db_w, wtall);
    cudaEventRecord(evD3, sB);

    // ---- one combined GEMM launch (hyper tiles first) ----
    cudaStreamWaitEvent(0, evKR, 0);
    cudaStreamWaitEvent(0, evHypW, 0);
    gemm_all<<<576, 256, G_SMEM>>>(ahyp, wtk, wtr, wthyp, bias, hyper_bias, px, phv, z);

    // ---- hyper pointwise ----
    hyper_pointwise<<<(BB * HHU + 255) / 256, 256>>>(z, hyper_c, out_ho, out_hc, aho);

    // ---- fused d-GEMM + gate combine -> s (64-row tiles, 2 CTAs/SM) ----
    cudaStreamWaitEvent(0, evD3, 0);
    gemm_s<<<dim3(FOURU/128, BB/64), 128, S_SMEM>>>(
        aho, wtall, dx_b, dh_b, db_b, px, phv, s);

    main_epilogue<<<BB, 512>>>(s, main_c, out_h, out_c);
}

// round 17
// speedup vs baseline: 1.4226x; 1.0076x over previous
#include <cuda_runtime.h>
#include <cuda_fp16.h>
#include <math.h>
#include <cstdint>

#define BB 2048
#define DD 1024
#define UU 1024
#define HHU 256
#define FOURU (4*UU)     // 4096
#define FOURHU (4*HHU)   // 1024
#define KHYP (DD+UU+HHU) // 2304
#define N3 (3*FOURU)     // 12288

// ---------------------------------------------------------------------------
// scratch (static device arrays; no allocation allowed)
// ---------------------------------------------------------------------------
__device__ float  g_z [BB * FOURHU];
__device__ __half g_s [BB * FOURU];    // fused gate pre-activations (fp16)
__device__ __half g_px[BB * FOURU];    // fp16 multipliers
__device__ __half g_ph[BB * FOURU];

// fp16 activations
__device__ __half g_ahyp[BB * KHYP];   // fp16 of [inputs|main_h|hyper_h]
__device__ __half g_aho [BB * HHU];    // fp16 of hyper_out
// transposed fp16 weights ([N, K] row-major, k-contiguous)
__device__ __half g_wthyp[FOURHU * KHYP];
__device__ __half g_wtall[N3 * HHU];   // dx_w^T | dh_w^T | db_w^T stacked on N
__device__ __half g_wtk[FOURU * UU];
__device__ __half g_wtr[FOURU * UU];

__device__ __forceinline__ float sigf(float x) { return 1.0f / (1.0f + expf(-x)); }

__device__ __forceinline__ uint32_t smem_u32(const void* p) {
    uint32_t a;
    asm("{ .reg .u64 t; cvta.to.shared.u64 t, %1; cvt.u32.u64 %0, t; }" : "=r"(a) : "l"(p));
    return a;
}
__device__ __forceinline__ void cpa16(uint32_t dst, const void* src) {
    asm volatile("cp.async.cg.shared.global [%0], [%1], 16;" :: "r"(dst), "l"(src));
}
#define CP_COMMIT() asm volatile("cp.async.commit_group;" ::: "memory")
#define CP_WAIT(n)  asm volatile("cp.async.wait_group %0;" :: "n"(n) : "memory")

__device__ __forceinline__ void ldsm4(uint32_t* r, uint32_t addr) {
    asm volatile("ldmatrix.sync.aligned.m8n8.x4.shared.b16 {%0,%1,%2,%3}, [%4];"
                 : "=r"(r[0]), "=r"(r[1]), "=r"(r[2]), "=r"(r[3]) : "r"(addr));
}
__device__ __forceinline__ void mma_f16(float* c, const uint32_t* a, uint32_t b0, uint32_t b1) {
    asm volatile("mma.sync.aligned.m16n8k16.row.col.f32.f16.f16.f32 "
                 "{%0,%1,%2,%3}, {%4,%5,%6,%7}, {%8,%9}, {%0,%1,%2,%3};"
                 : "+f"(c[0]), "+f"(c[1]), "+f"(c[2]), "+f"(c[3])
                 : "r"(a[0]), "r"(a[1]), "r"(a[2]), "r"(a[3]), "r"(b0), "r"(b1));
}

#define SROW 144

// ---------------------------------------------------------------------------
// 1-term GEMM core: C[M,N] = A[M,K] @ W[N,K]^T (+bias); OT = float or __half.
// CTA tile 128 x 256; 8 warps 2(m) x 4(n); warp tile 64x64; BK=64;
// 3-stage cp.async pipeline; 256 threads.
// ---------------------------------------------------------------------------
#define G_ABYTES (128 * SROW)                 // 18432
#define G_SSZ    ((128 + 256) * SROW)         // 55296
#define G_SMEM   (3 * G_SSZ)                  // 165888

template<typename OT>
__device__ __forceinline__
void gemm_core4(const __half* __restrict__ Ah, int lda,
                const __half* __restrict__ Wh, int ldw,
                const float* __restrict__ bias, OT* __restrict__ C,
                int N, int K, char* smem, int bx, int by)
{
    const uint32_t sb = smem_u32(smem);
    const int tid  = threadIdx.x;
    const int lane = tid & 31;
    const int wid  = tid >> 5;
    const int warp_m = wid & 1;
    const int warp_n = wid >> 1;
    const int m0 = by * 128;
    const int n0 = bx * 256;

    const __half* pAh = Ah + (size_t)m0 * lda;
    const __half* pWh = Wh + (size_t)n0 * ldw;

    float acc[4][8][4];
    #pragma unroll
    for (int a = 0; a < 4; a++)
        #pragma unroll
        for (int b = 0; b < 8; b++)
            #pragma unroll
            for (int c = 0; c < 4; c++) acc[a][b][c] = 0.0f;

    const uint32_t fr  = lane & 15;
    const uint32_t fcb = (lane >> 4) * 16;
    const int lr = tid >> 3;        // 0..31
    const int lc = tid & 7;
    const int nch = K / 64;

    auto load_stage = [&](uint32_t base, int k0) {
        #pragma unroll
        for (int i = 0; i < 4; i++) {
            int row = lr + i * 32;
            cpa16(base + row * SROW + lc * 16, pAh + (size_t)row * lda + k0 + lc * 8);
        }
        #pragma unroll
        for (int i = 0; i < 8; i++) {
            int row = lr + i * 32;
            cpa16(base + G_ABYTES + row * SROW + lc * 16, pWh + (size_t)row * ldw + k0 + lc * 8);
        }
    };

    load_stage(sb, 0);
    CP_COMMIT();
    load_stage(sb + G_SSZ, 64);
    CP_COMMIT();

    int buf = 0;
    int nbuf = 2;

    for (int kc = 0; kc < nch; kc++) {
        if (kc + 2 < nch) {
            load_stage(sb + nbuf * G_SSZ, (kc + 2) * 64);
            CP_COMMIT();
            nbuf = (nbuf == 2) ? 0 : nbuf + 1;
            CP_WAIT(2);
        } else if (kc + 1 < nch) {
            CP_WAIT(1);
        } else {
            CP_WAIT(0);
        }
        __syncthreads();

        const uint32_t stg = sb + buf * G_SSZ;
        buf = (buf == 2) ? 0 : buf + 1;
        #pragma unroll
        for (int s = 0; s < 4; s++) {
            const uint32_t kb = s * 32 + fcb;
            uint32_t ah[4][4];
            #pragma unroll
            for (int mt = 0; mt < 4; mt++)
                ldsm4(ah[mt], stg + (warp_m * 64 + mt * 16 + fr) * SROW + kb);
            #pragma unroll
            for (int np = 0; np < 4; np++) {
                uint32_t w[4];
                ldsm4(w, stg + G_ABYTES + (warp_n * 64 + np * 16 + fr) * SROW + kb);
                #pragma unroll
                for (int mt = 0; mt < 4; mt++) {
                    mma_f16(acc[mt][2*np],   ah[mt], w[0], w[2]);
                    mma_f16(acc[mt][2*np+1], ah[mt], w[1], w[3]);
                }
            }
        }
        __syncthreads();
    }

    const int er = lane >> 2;
    const int ec = (lane & 3) * 2;
    #pragma unroll
    for (int mt = 0; mt < 4; mt++) {
        const int row = m0 + warp_m * 64 + mt * 16 + er;
        #pragma unroll
        for (int nt = 0; nt < 8; nt++) {
            const int col = n0 + warp_n * 64 + nt * 8 + ec;
            float b0 = 0.f, b1 = 0.f;
            if (bias) { b0 = bias[col]; b1 = bias[col + 1]; }
            float v00 = acc[mt][nt][0] + b0, v01 = acc[mt][nt][1] + b1;
            float v10 = acc[mt][nt][2] + b0, v11 = acc[mt][nt][3] + b1;
            if constexpr (sizeof(OT) == 4) {
                *(float2*)((float*)C + (size_t)row * N + col) = make_float2(v00, v01);
                *(float2*)((float*)C + (size_t)(row + 8) * N + col) = make_float2(v10, v11);
            } else {
                *(__half2*)((__half*)C + (size_t)row * N + col) = __floats2half2_rn(v00, v01);
                *(__half2*)((__half*)C + (size_t)(row + 8) * N + col) = __floats2half2_rn(v10, v11);
            }
        }
    }
}

// ---------------------------------------------------------------------------
// gemm_all: hyper + px + ph in one flat-grid launch.
// blocks [0,64): hyper (N=1024, K=2304, fp32 z out) -- scheduled FIRST
// blocks [64,320): px (N=4096, K=1024, fp16 out)
// blocks [320,576): ph (N=4096, K=1024, fp16 out)
// ---------------------------------------------------------------------------
__global__ __launch_bounds__(256, 1)
void gemm_all(const __half* __restrict__ ahyp,
              const __half* __restrict__ wtk, const __half* __restrict__ wtr,
              const __half* __restrict__ wthyp,
              const float* __restrict__ bias, const float* __restrict__ hyper_bias,
              __half* __restrict__ px, __half* __restrict__ ph, float* __restrict__ z)
{
    extern __shared__ char smem[];
    const int b = blockIdx.x;
    if (b < 64) {
        gemm_core4<float>(ahyp, KHYP, wthyp, KHYP, hyper_bias, z, FOURHU, KHYP,
                          smem, b & 3, b >> 2);
    } else if (b < 320) {
        const int i = b - 64;
        gemm_core4<__half>(ahyp, KHYP, wtk, UU, bias, px, FOURU, UU,
                           smem, i & 15, i >> 4);
    } else {
        const int i = b - 320;
        gemm_core4<__half>(ahyp + DD, KHYP, wtr, UU, nullptr, ph, FOURU, UU,
                           smem, i & 15, i >> 4);
    }
}

// ---------------------------------------------------------------------------
// gemm_s: fused d_x/d_h/d_b GEMM + gate combine, fp16 px/ph via smem prefetch.
// CTA tile 64(m) x 128(n); 128 threads; 4 warps 1(m) x 4(n); warp tile 64x32.
// ~91 KB smem -> 2 CTAs/SM. Output s in fp16.
// ---------------------------------------------------------------------------
#define S_ATILE  (64 * SROW)               // 9216
#define S_WTILE  (128 * SROW)              // 18432
#define S_WOFF   (4 * S_ATILE)             // 36864
#define S_PXOFF  (S_WOFF + 2 * S_WTILE)    // 73728
#define S_PXROW  272                        // 128 halfs (256B) + 16B pad
#define S_SMEM   (S_PXOFF + 64 * S_PXROW)  // 91136

__global__ __launch_bounds__(128, 2)
void gemm_s(const __half* __restrict__ A,          // aho [2048,256]
            const __half* __restrict__ Wall,       // [12288,256]
            const float* __restrict__ bx, const float* __restrict__ bh,
            const float* __restrict__ bb,
            const __half* __restrict__ px, const __half* __restrict__ ph,
            __half* __restrict__ S)
{
    extern __shared__ char smem[];
    const uint32_t sb = smem_u32(smem);
    const int tid  = threadIdx.x;
    const int lane = tid & 31;
    const int warp_n = tid >> 5;            // 0..3
    const int m0 = blockIdx.y * 64;
    const int n0 = blockIdx.x * 128;

    const __half* pA = A + (size_t)m0 * HHU;

    const uint32_t fr  = lane & 15;
    const uint32_t fcb = (lane >> 4) * 16;
    const int lr = tid >> 3;                // 0..15
    const int lc = tid & 7;

    // load full A (4 chunks of 64x64 halfs)
    #pragma unroll
    for (int c = 0; c < 4; c++)
        #pragma unroll
        for (int i = 0; i < 4; i++) {
            int row = lr + i * 16;
            cpa16(sb + c * S_ATILE + row * SROW + lc * 16,
                  pA + (size_t)row * HHU + c * 64 + lc * 8);
        }
    auto load_w = [&](int t, int kc, int buf) {
        const __half* pW = Wall + (size_t)t * FOURU * HHU + (size_t)n0 * HHU;
        #pragma unroll
        for (int i = 0; i < 8; i++) {
            int row = lr + i * 16;
            cpa16(sb + S_WOFF + buf * S_WTILE + row * SROW + lc * 16,
                  pW + (size_t)row * HHU + kc * 64 + lc * 8);
        }
    };
    // prefetch a 64x128 fp16 tile of P (16KB)
    auto load_p = [&](const __half* __restrict__ P) {
        #pragma unroll
        for (int it = 0; it < 8; it++) {
            int idx = tid + it * 128;       // 0..1023
            int row = idx >> 4;             // 0..63
            int c16 = idx & 15;             // 0..15 (8 halfs each)
            cpa16(sb + S_PXOFF + row * S_PXROW + c16 * 16,
                  P + (size_t)(m0 + row) * FOURU + n0 + c16 * 8);
        }
    };

    load_w(0, 0, 0);
    CP_COMMIT();

    float s_acc[4][4][4];
    #pragma unroll
    for (int a = 0; a < 4; a++)
        #pragma unroll
        for (int b = 0; b < 4; b++)
            #pragma unroll
            for (int c = 0; c < 4; c++) s_acc[a][b][c] = 0.0f;

    float acc[4][4][4];
    #pragma unroll
    for (int a = 0; a < 4; a++)
        #pragma unroll
        for (int b = 0; b < 4; b++)
            #pragma unroll
            for (int c = 0; c < 4; c++) acc[a][b][c] = 0.0f;

    const int er = lane >> 2;
    const int ec = (lane & 3) * 2;

    for (int i = 0; i < 12; i++) {
        const int kc = i & 3;
        if (i + 1 < 12) {
            load_w((i + 1) >> 2, (i + 1) & 3, (i + 1) & 1);
            if (i == 0) load_p(px);   // used end of iter 3
            if (i == 4) load_p(ph);   // same buffer; used end of iter 7
            CP_COMMIT();
            CP_WAIT(1);
        } else {
            CP_WAIT(0);
        }
        __syncthreads();

        const uint32_t wb = sb + S_WOFF + (i & 1) * S_WTILE;
        const uint32_t ab = sb + kc * S_ATILE;
        #pragma unroll
        for (int s = 0; s < 4; s++) {
            const uint32_t kb = s * 32 + fcb;
            uint32_t ah[4][4];
            #pragma unroll
            for (int mt = 0; mt < 4; mt++)
                ldsm4(ah[mt], ab + (mt * 16 + fr) * SROW + kb);
            #pragma unroll
            for (int np = 0; np < 2; np++) {
                uint32_t w[4];
                ldsm4(w, wb + (warp_n * 32 + np * 16 + fr) * SROW + kb);
                #pragma unroll
                for (int mt = 0; mt < 4; mt++) {
                    mma_f16(acc[mt][2*np],   ah[mt], w[0], w[2]);
                    mma_f16(acc[mt][2*np+1], ah[mt], w[1], w[3]);
                }
            }
        }

        if (kc == 3) {
            const int t = i >> 2;
            #pragma unroll
            for (int mt = 0; mt < 4; mt++) {
                const int rl = mt * 16 + er;              // local row 0..63
                #pragma unroll
                for (int nt = 0; nt < 4; nt++) {
                    const int cl = warp_n * 32 + nt * 8 + ec;
                    const int col = n0 + cl;
                    if (t < 2) {
                        float2 p0 = __half22float2(
                            *(const __half2*)(smem + S_PXOFF + rl * S_PXROW + cl * 2));
                        float2 p1 = __half22float2(
                            *(const __half2*)(smem + S_PXOFF + (rl + 8) * S_PXROW + cl * 2));
                        const float* bp = (t == 0) ? bx : bh;
                        float b0 = bp[col], b1 = bp[col + 1];
                        s_acc[mt][nt][0] += (acc[mt][nt][0] + b0) * p0.x;
                        s_acc[mt][nt][1] += (acc[mt][nt][1] + b1) * p0.y;
                        s_acc[mt][nt][2] += (acc[mt][nt][2] + b0) * p1.x;
                        s_acc[mt][nt][3] += (acc[mt][nt][3] + b1) * p1.y;
                    } else {
                        float b0 = bb[col], b1 = bb[col + 1];
                        s_acc[mt][nt][0] += acc[mt][nt][0] + b0;
                        s_acc[mt][nt][1] += acc[mt][nt][1] + b1;
                        s_acc[mt][nt][2] += acc[mt][nt][2] + b0;
                        s_acc[mt][nt][3] += acc[mt][nt][3] + b1;
                    }
                    #pragma unroll
                    for (int c = 0; c < 4; c++) acc[mt][nt][c] = 0.0f;
                }
            }
        }
        __syncthreads();
    }

    #pragma unroll
    for (int mt = 0; mt < 4; mt++) {
        const int row = m0 + mt * 16 + er;
        #pragma unroll
        for (int nt = 0; nt < 4; nt++) {
            const int col = n0 + warp_n * 32 + nt * 8 + ec;
            *(__half2*)(S + (size_t)row * FOURU + col) =
                __floats2half2_rn(s_acc[mt][nt][0], s_acc[mt][nt][1]);
            *(__half2*)(S + (size_t)(row + 8) * FOURU + col) =
                __floats2half2_rn(s_acc[mt][nt][2], s_acc[mt][nt][3]);
        }
    }
}

// ---------------------------------------------------------------------------
// prep kernels
// ---------------------------------------------------------------------------
__global__ void concat_fp16(const float* __restrict__ inputs,
                            const float* __restrict__ main_h,
                            const float* __restrict__ hyper_h,
                            __half* __restrict__ Dh)
{
    int i4 = blockIdx.x * blockDim.x + threadIdx.x;
    if (i4 >= BB * KHYP / 4) return;
    int row = i4 / (KHYP / 4);
    int c4  = (i4 - row * (KHYP / 4)) * 4;
    const float* src;
    if (c4 < DD)            src = inputs  + (size_t)row * DD  + c4;
    else if (c4 < DD + UU)  src = main_h  + (size_t)row * UU  + (c4 - DD);
    else                    src = hyper_h + (size_t)row * HHU + (c4 - DD - UU);
    float4 v = *(const float4*)src;
    size_t o = (size_t)row * KHYP + c4;
    unsigned short hs[4];
    hs[0] = __half_as_ushort(__float2half_rn(v.x));
    hs[1] = __half_as_ushort(__float2half_rn(v.y));
    hs[2] = __half_as_ushort(__float2half_rn(v.z));
    hs[3] = __half_as_ushort(__float2half_rn(v.w));
    *(uint2*)(Dh + o) = make_uint2((uint32_t)hs[0] | ((uint32_t)hs[1] << 16),
                                   (uint32_t)hs[2] | ((uint32_t)hs[3] << 16));
}

__device__ __forceinline__ void trans_tile(const float* __restrict__ W,
                                           __half* __restrict__ Th,
                                           int N, int dstLd, int kOff,
                                           int n0, int k0)
{
    __shared__ float t[64][33];
    const int tx = threadIdx.x, ty = threadIdx.y;   // 32 x 8
    #pragma unroll
    for (int i = 0; i < 8; i++)
        t[ty + i * 8][tx] = W[(size_t)(k0 + ty + i * 8) * N + n0 + tx];
    __syncthreads();
    #pragma unroll
    for (int j = 0; j < 4; j++) {
        int n = ty + j * 8;
        float v0 = t[tx * 2][n], v1 = t[tx * 2 + 1][n];
        uint32_t pk = (uint32_t)__half_as_ushort(__float2half_rn(v0))
                    | ((uint32_t)__half_as_ushort(__float2half_rn(v1)) << 16);
        *(uint32_t*)(Th + (size_t)(n0 + n) * dstLd + kOff + k0 + tx * 2) = pk;
    }
}

__global__ void trans_d3(const float* __restrict__ w0, const float* __restrict__ w1,
                         const float* __restrict__ w2, __half* __restrict__ Tall)
{
    const float* W = (blockIdx.z == 0) ? w0 : (blockIdx.z == 1) ? w1 : w2;
    trans_tile(W, Tall + (size_t)blockIdx.z * FOURU * HHU, FOURU, HHU, 0,
               blockIdx.x * 32, blockIdx.y * 64);
}

__global__ void trans_kr(const float* __restrict__ kw, const float* __restrict__ rw,
                         __half* __restrict__ Tk, __half* __restrict__ Tr)
{
    const float* W = blockIdx.z ? rw : kw;
    __half* T = blockIdx.z ? Tr : Tk;
    trans_tile(W, T, FOURU, UU, 0, blockIdx.x * 32, blockIdx.y * 64);
}

__global__ void trans_hyp(const float* __restrict__ hk, const float* __restrict__ hr,
                          __half* __restrict__ T)
{
    if (blockIdx.z == 0) {
        trans_tile(hk, T, FOURHU, KHYP, 0, blockIdx.x * 32, blockIdx.y * 64);
    } else {
        if (blockIdx.y >= HHU / 64) return;
        trans_tile(hr, T, FOURHU, KHYP, DD + UU, blockIdx.x * 32, blockIdx.y * 64);
    }
}

// ---------------------------------------------------------------------------
// hyper LSTM pointwise (+ fp16 of hyper_out)
// ---------------------------------------------------------------------------
__global__ void hyper_pointwise(const float* __restrict__ z,
                                const float* __restrict__ hyper_c,
                                float* __restrict__ hyper_out,
                                float* __restrict__ hyper_c_new,
                                __half* __restrict__ hoh)
{
    int idx = blockIdx.x * blockDim.x + threadIdx.x;
    if (idx >= BB * HHU) return;
    int b = idx / HHU;
    int u = idx - b * HHU;
    const float* zr = z + (size_t)b * FOURHU;
    float hi = zr[u];
    float hf = zr[HHU + u];
    float hg = zr[2 * HHU + u];
    float ho = zr[3 * HHU + u];
    float c = sigf(hf) * hyper_c[idx] + sigf(hi) * tanhf(hg);
    hyper_c_new[idx] = c;
    float out = sigf(ho) * tanhf(c);
    hyper_out[idx] = out;
    hoh[idx] = __float2half_rn(out);
}

// ---------------------------------------------------------------------------
// LN epilogue: S is fp16; thread t handles cols (2t, 2t+1) of each gate.
// ---------------------------------------------------------------------------
__device__ __forceinline__ void block_reduce2(float& a, float& b, float* sm)
{
    __syncthreads();
    #pragma unroll
    for (int o = 16; o > 0; o >>= 1) {
        a += __shfl_down_sync(0xffffffffu, a, o);
        b += __shfl_down_sync(0xffffffffu, b, o);
    }
    int w = threadIdx.x >> 5, l = threadIdx.x & 31;
    if (l == 0) { sm[w] = a; sm[32 + w] = b; }
    __syncthreads();
    if (w == 0) {
        int nw = blockDim.x >> 5;
        a = (l < nw) ? sm[l] : 0.0f;
        b = (l < nw) ? sm[32 + l] : 0.0f;
        #pragma unroll
        for (int o = 16; o > 0; o >>= 1) {
            a += __shfl_down_sync(0xffffffffu, a, o);
            b += __shfl_down_sync(0xffffffffu, b, o);
        }
        if (l == 0) { sm[0] = a; sm[32] = b; }
    }
    __syncthreads();
    a = sm[0];
    b = sm[32];
}

__global__ __launch_bounds__(512)
void main_epilogue(const __half* __restrict__ S, const float* __restrict__ main_c,
                   float* __restrict__ out_h, float* __restrict__ out_c)
{
    __shared__ float sm[64];
    const int b = blockIdx.x;
    const int t = threadIdx.x;
    const __half2* Sr = (const __half2*)(S + (size_t)b * FOURU);  // 2048 half2

    float2 gv[4];
    float sum = 0.0f, sq = 0.0f;
    #pragma unroll
    for (int g = 0; g < 4; g++) {
        gv[g] = __half22float2(Sr[g * 512 + t]);
        sum += gv[g].x + gv[g].y;
        sq = fmaf(gv[g].x, gv[g].x, fmaf(gv[g].y, gv[g].y, sq));
    }
    block_reduce2(sum, sq, sm);
    float mean = sum * (1.0f / 4096.0f);
    float var = sq * (1.0f / 4096.0f) - mean * mean;
    float inv = rsqrtf(var + 1e-3f);

    float i0 = (gv[0].x - mean) * inv, i1 = (gv[0].y - mean) * inv;
    float f0 = (gv[1].x - mean) * inv, f1 = (gv[1].y - mean) * inv;
    float g0 = (gv[2].x - mean) * inv, g1 = (gv[2].y - mean) * inv;
    float o0 = (gv[3].x - mean) * inv, o1 = (gv[3].y - mean) * inv;

    const size_t cb = (size_t)b * UU;
    float2 cprev = *(const float2*)(main_c + cb + 2 * t);
    float c0 = sigf(f0) * cprev.x + sigf(i0) * tanhf(g0);
    float c1 = sigf(f1) * cprev.y + sigf(i1) * tanhf(g1);

    float sum2 = c0 + c1;
    float sq2 = fmaf(c0, c0, c1 * c1);
    block_reduce2(sum2, sq2, sm);
    float mean2 = sum2 * (1.0f / 1024.0f);
    float var2 = sq2 * (1.0f / 1024.0f) - mean2 * mean2;
    float inv2 = rsqrtf(var2 + 1e-3f);

    float h0 = sigf(o0) * tanhf((c0 - mean2) * inv2);
    float h1 = sigf(o1) * tanhf((c1 - mean2) * inv2);

    *(float2*)(out_c + cb + 2 * t) = make_float2(c0, c1);
    *(float2*)(out_h + cb + 2 * t) = make_float2(h0, h1);
}

// ---------------------------------------------------------------------------
// launch
// ---------------------------------------------------------------------------
static cudaStream_t make_stream() {
    cudaStream_t s;
    cudaStreamCreateWithFlags(&s, cudaStreamNonBlocking);
    return s;
}
static cudaEvent_t make_event() {
    cudaEvent_t e;
    cudaEventCreateWithFlags(&e, cudaEventDisableTiming);
    return e;
}

extern "C" void kernel_launch(void* const* d_in, const int* in_sizes, int n_in,
                              void* d_out, int out_size)
{
    const float* inputs       = (const float*)d_in[0];
    const float* main_h       = (const float*)d_in[1];
    const float* main_c       = (const float*)d_in[2];
    const float* hyper_h      = (const float*)d_in[3];
    const float* hyper_c      = (const float*)d_in[4];
    const float* kernel_w     = (const float*)d_in[5];
    const float* rec_w        = (const float*)d_in[6];
    const float* bias         = (const float*)d_in[7];
    const float* hyper_kernel = (const float*)d_in[8];
    const float* hyper_rec    = (const float*)d_in[9];
    const float* hyper_bias   = (const float*)d_in[10];
    const float* dx_w         = (const float*)d_in[11];
    const float* dx_b         = (const float*)d_in[12];
    const float* dh_w         = (const float*)d_in[13];
    const float* dh_b         = (const float*)d_in[14];
    const float* db_w         = (const float*)d_in[15];
    const float* db_b         = (const float*)d_in[16];

    float* out = (float*)d_out;
    float* out_h  = out;
    float* out_c  = out + (size_t)BB * UU;
    float* out_ho = out + (size_t)2 * BB * UU;
    float* out_hc = out_ho + (size_t)BB * HHU;

    float *z;
    __half *s, *px, *phv;
    cudaGetSymbolAddress((void**)&z,   g_z);
    cudaGetSymbolAddress((void**)&s,   g_s);
    cudaGetSymbolAddress((void**)&px,  g_px);
    cudaGetSymbolAddress((void**)&phv, g_ph);

    __half *ahyp, *aho, *wthyp, *wtall, *wtk, *wtr;
    cudaGetSymbolAddress((void**)&ahyp,  g_ahyp);
    cudaGetSymbolAddress((void**)&aho,   g_aho);
    cudaGetSymbolAddress((void**)&wthyp, g_wthyp);
    cudaGetSymbolAddress((void**)&wtall, g_wtall);
    cudaGetSymbolAddress((void**)&wtk,   g_wtk);
    cudaGetSymbolAddress((void**)&wtr,   g_wtr);

    cudaFuncSetAttribute(gemm_all, cudaFuncAttributeMaxDynamicSharedMemorySize, G_SMEM);
    cudaFuncSetAttribute(gemm_s,   cudaFuncAttributeMaxDynamicSharedMemorySize, S_SMEM);

    // One-time resources (created outside capture on first call; reused after).
    static cudaStream_t sB = make_stream();
    static cudaStream_t sC = make_stream();
    static cudaEvent_t evRoot  = make_event();
    static cudaEvent_t evHypW  = make_event();
    static cudaEvent_t evD3    = make_event();
    static cudaEvent_t evKR    = make_event();

    dim3 tb(32, 8);

    // ---- fork side streams at graph root ----
    cudaEventRecord(evRoot, 0);
    cudaStreamWaitEvent(sB, evRoot, 0);
    cudaStreamWaitEvent(sC, evRoot, 0);

    // three concurrent prep branches
    concat_fp16<<<(BB * KHYP / 4 + 255) / 256, 256>>>(inputs, main_h, hyper_h, ahyp);

    trans_kr<<<dim3(FOURU/32, UU/64, 2), tb, 0, sC>>>(kernel_w, rec_w, wtk, wtr);
    cudaEventRecord(evKR, sC);

    trans_hyp<<<dim3(FOURHU/32, (DD+UU)/64, 2), tb, 0, sB>>>(hyper_kernel, hyper_rec, wthyp);
    cudaEventRecord(evHypW, sB);
    trans_d3 <<<dim3(FOURU/32, HHU/64, 3), tb, 0, sB>>>(dx_w, dh_w, db_w, wtall);
    cudaEventRecord(evD3, sB);

    // ---- one combined GEMM launch (hyper tiles first) ----
    cudaStreamWaitEvent(0, evKR, 0);
    cudaStreamWaitEvent(0, evHypW, 0);
    gemm_all<<<576, 256, G_SMEM>>>(ahyp, wtk, wtr, wthyp, bias, hyper_bias, px, phv, z);

    // ---- hyper pointwise ----
    hyper_pointwise<<<(BB * HHU + 255) / 256, 256>>>(z, hyper_c, out_ho, out_hc, aho);

    // ---- fused d-GEMM + gate combine -> s (64-row tiles, 2 CTAs/SM) ----
    cudaStreamWaitEvent(0, evD3, 0);
    gemm_s<<<dim3(FOURU/128, BB/64), 128, S_SMEM>>>(
        aho, wtall, dx_b, dh_b, db_b, px, phv, s);

    main_epilogue<<<BB, 512>>>(s, main_c, out_h, out_c);
}